// round 13
// baseline (speedup 1.0000x reference)
#include <cuda_runtime.h>
#include <cuda_bf16.h>
#include <cuda_fp16.h>
#include <cstdint>
#include <math.h>

#define BB 16
#define NN_ 1024
#define EDIM 16
#define WINDOW 12
#define NNSQ (NN_*NN_)
#define BNN (BB*NNSQ)
#define HALF_BNN (BNN/2)
#define OFF_MASK (BB*NN_*64)
#define OFF_LOSS (OFF_MASK + BNN)
#define MASK_THR (-2.66352776f)   /* ln(1.4) - 3 */

// ---------------- scratch ----------------
__device__ float g_E[NN_*EDIM];
__device__ float g_Et[EDIM*NN_];
__device__ float g_EM[NNSQ];
__device__ float g_supports[NNSQ];
__device__ __half g_sh[(size_t)BNN];
__device__ uint32_t g_bits[BNN/32];
__device__ __half g_xh[(size_t)BB*NN_*128];
__device__ __half g_xl[(size_t)BB*NN_*128];
__device__ __half g_zh[(size_t)BB*NN_*64];
__device__ __half g_zl[(size_t)BB*NN_*64];
__device__ __half g_Wn_r[(size_t)NN_*256*128];
__device__ __half g_Wn_u[(size_t)NN_*256*64];
__device__ float g_bias_r[NN_*128];
__device__ float g_bias_u[NN_*64];
__device__ float g_xb[(size_t)BB*NN_*128];
__device__ float g_zs[(size_t)BB*NN_*64];
__device__ float g_rb[(size_t)BB*NN_*64];
__device__ float g_c2[(size_t)BB*NN_*64];
__device__ unsigned int g_pos[BB];
__device__ unsigned int g_kept[BB];

// ---------------- helpers ----------------
__device__ __forceinline__ float warpSum(float v){
  #pragma unroll
  for (int o=16;o;o>>=1) v += __shfl_xor_sync(0xffffffffu, v, o);
  return v;
}
__device__ __forceinline__ float blockSum(float v, float* red){
  int lane = threadIdx.x & 31, w = threadIdx.x >> 5;
  int nw = blockDim.x >> 5;
  v = warpSum(v);
  __syncthreads();
  if (lane==0) red[w] = v;
  __syncthreads();
  float r = (threadIdx.x < (unsigned)nw) ? red[threadIdx.x] : 0.0f;
  if (w==0) r = warpSum(r);
  if (threadIdx.x==0) red[0] = r;
  __syncthreads();
  return red[0];
}
__device__ __forceinline__ uint32_t rotl32(uint32_t x, int r){
  return __funnelshift_l(x, x, r);
}
__device__ __forceinline__ void threefry2x32(uint32_t k0, uint32_t k1,
                                             uint32_t& x0, uint32_t& x1){
  uint32_t ks0 = k0, ks1 = k1, ks2 = k0 ^ k1 ^ 0x1BD11BDAu;
  x0 += ks0; x1 += ks1;
  const int R0[4] = {13,15,26,6};
  const int R1[4] = {17,29,16,24};
  uint32_t ks[3] = {ks0, ks1, ks2};
  #pragma unroll
  for (int i=0;i<5;i++){
    #pragma unroll
    for (int j=0;j<4;j++){
      int r = (i & 1) ? R1[j] : R0[j];
      x0 += x1; x1 = rotl32(x1, r); x1 ^= x0;
    }
    x0 += ks[(i+1)%3];
    x1 += ks[(i+2)%3] + (uint32_t)(i+1);
  }
}
__device__ __forceinline__ void split_h16(float v, __half& h, __half& l){
  h = __float2half_rn(v);
  l = __float2half_rn(v - __half2float(h));
}
__device__ __forceinline__ uint32_t pack_h2(__half a, __half b){
  __half2 p(a, b);
  return *reinterpret_cast<uint32_t*>(&p);
}
__device__ __forceinline__ void ldsm4(uint32_t& r0,uint32_t& r1,uint32_t& r2,uint32_t& r3,
                                      const __half* p){
  uint32_t a = (uint32_t)__cvta_generic_to_shared(p);
  asm volatile("ldmatrix.sync.aligned.m8n8.x4.shared.b16 {%0,%1,%2,%3},[%4];"
    : "=r"(r0),"=r"(r1),"=r"(r2),"=r"(r3) : "r"(a));
}
__device__ __forceinline__ void ldsm2t(uint32_t& r0,uint32_t& r1, const __half* p){
  uint32_t a = (uint32_t)__cvta_generic_to_shared(p);
  asm volatile("ldmatrix.sync.aligned.m8n8.x2.trans.shared.b16 {%0,%1},[%2];"
    : "=r"(r0),"=r"(r1) : "r"(a));
}
__device__ __forceinline__ void mma16816h(float* c, const uint32_t* a, const uint32_t* b){
  asm volatile("mma.sync.aligned.m16n8k16.row.col.f32.f16.f16.f32 "
    "{%0,%1,%2,%3},{%4,%5,%6,%7},{%8,%9},{%0,%1,%2,%3};"
    : "+f"(c[0]),"+f"(c[1]),"+f"(c[2]),"+f"(c[3])
    : "r"(a[0]),"r"(a[1]),"r"(a[2]),"r"(a[3]), "r"(b[0]),"r"(b[1]));
}
__device__ __forceinline__ float prob_from_pos(){
  unsigned int tot = 0;
  #pragma unroll
  for (int i=0;i<BB;i++) tot += g_pos[i];
  float active = (float)tot / (float)BNN;
  return fminf(0.05f/active + 1e-8f, 1.0f);
}

// ---------------- kernels ----------------

__global__ void k_setup(const float* __restrict__ we, const int* __restrict__ itp){
  int tid = blockIdx.x*blockDim.x + threadIdx.x;
  float it = (float)itp[0];
  if (tid < NN_*EDIM){
    int d = tid & 15;
    int pair = d >> 1;
    float arg = (float)((double)(2*pair) * (-9.210340371976184/16.0));
    float div = expf(arg);
    float pe = (d & 1) ? cosf(it*div) : sinf(it*div);
    float e = we[tid] + pe;
    g_E[tid] = e;
    g_Et[d*NN_ + (tid>>4)] = e;
  }
  if (blockIdx.x==0 && threadIdx.x < 2*BB){
    if (threadIdx.x < BB) g_pos[threadIdx.x] = 0u;
    else                  g_kept[threadIdx.x-BB] = 0u;
  }
}

// [0,1024) em+bias, [1024,2048) supports.
__global__ void k_pre(const float* __restrict__ mp,
                      const float* __restrict__ bpr, const float* __restrict__ bpu){
  int g = blockIdx.x;
  if (g < NN_){
    int n = g;
    __shared__ float en[EDIM];
    if (threadIdx.x < EDIM) en[threadIdx.x] = g_E[n*EDIM+threadIdx.x];
    __syncthreads();
    int m0 = threadIdx.x*4;
    float4 a = make_float4(0.f,0.f,0.f,0.f);
    #pragma unroll
    for (int d=0; d<EDIM; d++){
      float4 mv = *(const float4*)&mp[d*NN_+m0];
      float e = en[d];
      a.x += e*mv.x; a.y += e*mv.y; a.z += e*mv.z; a.w += e*mv.w;
    }
    *(float4*)&g_EM[n*NN_+m0] = a;
    int o = threadIdx.x;
    if (o < 128){
      float br = 0.f;
      #pragma unroll
      for (int d=0; d<EDIM; d++) br += en[d]*bpr[d*128+o];
      g_bias_r[n*128+o] = br;
      if (o < 64){
        float bu = 0.f;
        #pragma unroll
        for (int d=0; d<EDIM; d++) bu += en[d]*bpu[d*64+o];
        g_bias_u[n*64+o] = bu;
      }
    }
  } else {
    int n = g - NN_;
    __shared__ float row[NN_];
    __shared__ float red[32];
    float en[EDIM];
    #pragma unroll
    for (int d=0; d<EDIM; d++) en[d] = g_E[n*EDIM+d];
    int m0 = threadIdx.x*4;
    float4 a = make_float4(0.f,0.f,0.f,0.f);
    #pragma unroll
    for (int d=0; d<EDIM; d++){
      float4 ev = *(const float4*)&g_Et[d*NN_+m0];
      float e = en[d];
      a.x += e*ev.x; a.y += e*ev.y; a.z += e*ev.z; a.w += e*ev.w;
    }
    a.x = __expf(fmaxf(a.x,0.f)); a.y = __expf(fmaxf(a.y,0.f));
    a.z = __expf(fmaxf(a.z,0.f)); a.w = __expf(fmaxf(a.w,0.f));
    *(float4*)&row[m0] = a;
    float s = blockSum(a.x+a.y+a.z+a.w, red);
    float inv = 1.0f/s;
    float4 r4 = *(float4*)&row[m0];
    r4.x *= inv; r4.y *= inv; r4.z *= inv; r4.w *= inv;
    *(float4*)&g_supports[n*NN_+m0] = r4;
  }
}

// prep: cat(x,state) -> fp16 hi/lo
__global__ void k_prep(const float* __restrict__ x, const float* __restrict__ st){
  int q = blockIdx.x*256 + threadIdx.x;
  int t4 = q*4;
  int j = t4 & 127; int bn = t4 >> 7;
  float4 v = (j < 64) ? *(const float4*)&x[(size_t)bn*64 + j]
                      : *(const float4*)&st[(size_t)bn*64 + (j-64)];
  __half h0,l0,h1,l1,h2,l2,h3,l3;
  split_h16(v.x,h0,l0); split_h16(v.y,h1,l1);
  split_h16(v.z,h2,l2); split_h16(v.w,h3,l3);
  *(uint2*)&g_xh[t4] = make_uint2(pack_h2(h0,h1), pack_h2(h2,h3));
  *(uint2*)&g_xl[t4] = make_uint2(pack_h2(l0,l1), pack_h2(l2,l3));
}

// Wn[n,i2,o] = sum_d E[n,d] * Wp[d,i2,o] -> fp16 (standalone, on stream s2)
template<int OC>
__device__ __forceinline__ void wgen_body(const float* __restrict__ Wp, __half* __restrict__ Wn,
                                          int lb, float* Esm){
  constexpr int NQ = OC/4;
  constexpr int NI = 256/NQ;
  int n0 = (lb>>4)*64;
  int i20 = (lb&15)*16;
  int t = threadIdx.x;
  int oq = t % NQ, ig = t / NQ;
  for (int q=t; q<64*EDIM; q+=256)
    Esm[q] = g_E[(n0 + (q>>4))*EDIM + (q&15)];
  __syncthreads();
  for (int ii=ig; ii<16; ii+=NI){
    int i2 = i20+ii;
    float4 w[EDIM];
    #pragma unroll
    for (int d=0; d<EDIM; d++)
      w[d] = *(const float4*)&Wp[((size_t)d*256 + i2)*OC + oq*4];
    #pragma unroll 4
    for (int nn=0; nn<64; nn++){
      float4 a = make_float4(0.f,0.f,0.f,0.f);
      #pragma unroll
      for (int d=0; d<EDIM; d++){
        float e = Esm[nn*EDIM + d];
        a.x += e*w[d].x; a.y += e*w[d].y; a.z += e*w[d].z; a.w += e*w[d].w;
      }
      __half2 h01 = __floats2half2_rn(a.x, a.y);
      __half2 h23 = __floats2half2_rn(a.z, a.w);
      *(uint2*)&Wn[((size_t)(n0+nn)*256 + i2)*OC + oq*4] =
          make_uint2(*(uint32_t*)&h01, *(uint32_t*)&h23);
    }
  }
}
__global__ void __launch_bounds__(256) k_wgen(const float* __restrict__ Wpr,
                                              const float* __restrict__ Wpu){
  __shared__ float Esm[64*EDIM];
  int lb = blockIdx.x;
  if (lb < 256) wgen_body<128>(Wpr, g_Wn_r, lb, Esm);
  else          wgen_body<64>(Wpu, g_Wn_u, lb-256, Esm);
}

// Pure supmask: 1024 blocks x 16 rows (2x 8-row passes), reg-capped for occupancy.
__global__ void __launch_bounds__(256,3) k_supmask(
    const float* __restrict__ T, const float* __restrict__ TP,
    const float* __restrict__ gamma, const float* __restrict__ beta,
    float* __restrict__ out_mask){
  __shared__ float red[8][8];
  __shared__ float inv8[8];
  int id = blockIdx.x;
  int b = id >> 6;
  int n0base = (id & 63)*16;
  extern __shared__ float sm[];
  float* Tsm = sm;                          // 48 KB
  int tid = threadIdx.x, lane = tid & 31, wrp = tid >> 5;
  {
    const float4* Tg = (const float4*)(T + (size_t)b*WINDOW*NN_);
    float4* T4 = (float4*)Tsm;
    #pragma unroll
    for (int i=0;i<12;i++) T4[tid + i*256] = Tg[tid + i*256];
  }
  __syncthreads();
  int m0 = tid*4;
  const float bni = 1.0f/sqrtf(1.0f + 1e-5f);
  unsigned int cnt = 0;
  #pragma unroll 1
  for (int half=0; half<2; half++){
    int n0 = n0base + half*8;
    float tg[8][4];
    #pragma unroll
    for (int r=0;r<8;r++){ tg[r][0]=0.f; tg[r][1]=0.f; tg[r][2]=0.f; tg[r][3]=0.f; }
    #pragma unroll
    for (int w=0; w<WINDOW; w++){
      float4 tw = *(float4*)&Tsm[w*NN_+m0];
      #pragma unroll
      for (int r=0;r<8;r++){
        float tvs = Tsm[w*NN_ + n0 + r];
        tg[r][0] += tvs*tw.x; tg[r][1] += tvs*tw.y;
        tg[r][2] += tvs*tw.z; tg[r][3] += tvs*tw.w;
      }
    }
    float psum[8];
    #pragma unroll
    for (int r=0;r<8;r++){
      tg[r][0] = __expf(fmaxf(tg[r][0],0.f));
      tg[r][1] = __expf(fmaxf(tg[r][1],0.f));
      tg[r][2] = __expf(fmaxf(tg[r][2],0.f));
      tg[r][3] = __expf(fmaxf(tg[r][3],0.f));
      psum[r] = (tg[r][0]+tg[r][1])+(tg[r][2]+tg[r][3]);
    }
    #pragma unroll
    for (int r=0;r<8;r++) psum[r] = warpSum(psum[r]);
    __syncthreads();
    if (lane==0){
      #pragma unroll
      for (int r=0;r<8;r++) red[r][wrp] = psum[r];
    }
    __syncthreads();
    if (tid < 8){
      float s = 0.f;
      #pragma unroll
      for (int k=0;k<8;k++) s += red[tid][k];
      inv8[tid] = 1.0f/s;
    }
    __syncthreads();
    float rm[8][4];
    #pragma unroll
    for (int r=0;r<8;r++){
      float4 t = *(const float4*)&g_EM[(size_t)(n0+r)*NN_ + m0];
      rm[r][0]=t.x; rm[r][1]=t.y; rm[r][2]=t.z; rm[r][3]=t.w;
    }
    #pragma unroll
    for (int w=0; w<WINDOW; w++){
      float4 tp = __ldg((const float4*)&TP[w*NN_+m0]);
      #pragma unroll
      for (int r=0;r<8;r++){
        float tvs = Tsm[w*NN_ + n0 + r];
        rm[r][0] += tvs*tp.x; rm[r][1] += tvs*tp.y;
        rm[r][2] += tvs*tp.z; rm[r][3] += tvs*tp.w;
      }
    }
    #pragma unroll
    for (int r=0;r<8;r++){
      int n = n0 + r;
      float sc = bni*gamma[n], bt = beta[n];
      float v0 = rm[r][0]*sc + bt, v1 = rm[r][1]*sc + bt;
      float v2 = rm[r][2]*sc + bt, v3 = rm[r][3]*sc + bt;
      uint32_t nib = (v0 > MASK_THR ? 1u:0u) | (v1 > MASK_THR ? 2u:0u)
                   | (v2 > MASK_THR ? 4u:0u) | (v3 > MASK_THR ? 8u:0u);
      float4 mk = make_float4(nib&1u?1.f:0.f, nib&2u?1.f:0.f, nib&4u?1.f:0.f, nib&8u?1.f:0.f);
      size_t idx = (size_t)b*NNSQ + (size_t)n*NN_ + m0;
      *(float4*)&out_mask[idx] = mk;
      float inv = inv8[r];
      float4 sp = *(const float4*)&g_supports[n*NN_+m0];
      sp.x = (sp.x + tg[r][0]*inv)*0.5f*mk.x;
      sp.y = (sp.y + tg[r][1]*inv)*0.5f*mk.y;
      sp.z = (sp.z + tg[r][2]*inv)*0.5f*mk.z;
      sp.w = (sp.w + tg[r][3]*inv)*0.5f*mk.w;
      *(uint2*)&g_sh[idx] = make_uint2(
          pack_h2(__float2half_rn(sp.x), __float2half_rn(sp.y)),
          pack_h2(__float2half_rn(sp.z), __float2half_rn(sp.w)));
      cnt += __popc(nib);
      uint32_t v = nib << ((lane&7)*4);
      v |= __shfl_xor_sync(0xffffffffu, v, 1);
      v |= __shfl_xor_sync(0xffffffffu, v, 2);
      v |= __shfl_xor_sync(0xffffffffu, v, 4);
      if ((lane&7)==0) g_bits[idx>>5] = v;
    }
  }
  __syncthreads();
  float fc = blockSum((float)cnt, (float*)red);
  if (tid==0) atomicAdd(&g_pos[b], (unsigned int)(fc + 0.5f));
}

// kept-count on stream s2 (after wgen; waits on supmask via event).
__global__ void __launch_bounds__(256) k_kept(){
  __shared__ unsigned int cnt[BB];
  if (threadIdx.x < BB) cnt[threadIdx.x] = 0u;
  __syncthreads();
  float prob = prob_from_pos();
  int lane = threadIdx.x & 31;
  unsigned int base = blockIdx.x*1024u + threadIdx.x;
  #pragma unroll
  for (int k=0;k<4;k++){
    unsigned int t = base + (unsigned)k*256u;
    uint32_t x0 = t, x1 = t + (uint32_t)HALF_BNN;
    threefry2x32(0u, 42u, x0, x1);
    float u0 = __uint_as_float((x0>>9) | 0x3f800000u) - 1.0f;
    float u1 = __uint_as_float((x1>>9) | 0x3f800000u) - 1.0f;
    uint32_t w0 = g_bits[t>>5];
    uint32_t w1 = g_bits[(t + HALF_BNN)>>5];
    int b0 = (int)(t >> 20);
    bool keep0 = ((w0>>lane)&1u) && !(u0 < prob);
    bool keep1 = ((w1>>lane)&1u) && !(u1 < prob);
    unsigned bal0 = __ballot_sync(0xffffffffu, keep0);
    unsigned bal1 = __ballot_sync(0xffffffffu, keep1);
    if (lane==0){
      if (bal0) atomicAdd(&cnt[b0],   __popc(bal0));
      if (bal1) atomicAdd(&cnt[b0+8], __popc(bal1));
    }
  }
  __syncthreads();
  if (threadIdx.x < BB && cnt[threadIdx.x]) atomicAdd(&g_kept[threadIdx.x], cnt[threadIdx.x]);
}

// mma<128>: 512 threads, A=fp16 sup, B=fp16 hi/lo; double-buffered + prefetch.
__global__ void __launch_bounds__(512) k_mma128(const __half* __restrict__ Bh,
                                                const __half* __restrict__ Bl,
                                                float* __restrict__ C){
  constexpr int NO = 128;
  constexpr int BST = NO+8;
  constexpr int APITCH = 40;
  __shared__ __half Ash[2][128*APITCH];
  __shared__ __half Bsh[2][32*BST], Bsl[2][32*BST];
  int b = blockIdx.x >> 3;
  int m0 = (blockIdx.x & 7)*128;
  int w = threadIdx.x>>5, lane = threadIdx.x&31;
  int wm = (w>>1)*16;
  int wn = (w&1)*64;
  float acc[8][4];
  #pragma unroll
  for (int j=0;j<8;j++){ acc[j][0]=0.f; acc[j][1]=0.f; acc[j][2]=0.f; acc[j][3]=0.f; }
  const __half* Ahb = g_sh + (size_t)b*NNSQ;
  const __half* Bhb = Bh + (size_t)b*NN_*NO;
  const __half* Blb = Bl + (size_t)b*NN_*NO;
  int ar = threadIdx.x>>2, ac = threadIdx.x&3;
  int brr = threadIdx.x>>4, bc = threadIdx.x&15;
  uint4 pAh, pBh, pBl;
  auto ldtile = [&](int k0){
    pAh = *(const uint4*)&Ahb[(size_t)(m0+ar)*NN_ + k0 + ac*8];
    pBh = *(const uint4*)&Bhb[(size_t)(k0+brr)*NO + bc*8];
    pBl = *(const uint4*)&Blb[(size_t)(k0+brr)*NO + bc*8];
  };
  auto sttile = [&](int buf){
    *(uint4*)&Ash[buf][ar*APITCH + ac*8] = pAh;
    *(uint4*)&Bsh[buf][brr*BST + bc*8] = pBh;
    *(uint4*)&Bsl[buf][brr*BST + bc*8] = pBl;
  };
  ldtile(0);
  sttile(0);
  __syncthreads();
  #pragma unroll 1
  for (int t=0;t<32;t++){
    if (t+1 < 32) ldtile((t+1)*32);
    int buf = t & 1;
    #pragma unroll
    for (int kk=0; kk<2; kk++){
      uint32_t ah[4];
      int aoff = (wm + (lane&15))*APITCH + kk*16 + (lane>>4)*8;
      ldsm4(ah[0],ah[1],ah[2],ah[3], &Ash[buf][aoff]);
      #pragma unroll
      for (int j=0;j<8;j++){
        uint32_t bh[2], bl[2];
        int boff = (kk*16 + (lane&15))*BST + wn + j*8;
        ldsm2t(bh[0],bh[1], &Bsh[buf][boff]);
        ldsm2t(bl[0],bl[1], &Bsl[buf][boff]);
        mma16816h(acc[j], ah, bh);
        mma16816h(acc[j], ah, bl);
      }
    }
    if (t+1 < 32){
      __syncthreads();
      sttile((t+1)&1);
      __syncthreads();
    }
  }
  #pragma unroll
  for (int j=0;j<8;j++){
    int r0 = m0 + wm + (lane>>2);
    int c0 = wn + j*8 + (lane&3)*2;
    float* Cp = C + ((size_t)b*NN_ + r0)*NO + c0;
    Cp[0] = acc[j][0]; Cp[1] = acc[j][1];
    Cp[(size_t)8*NO] = acc[j][2]; Cp[(size_t)8*NO+1] = acc[j][3];
  }
}

// mma<64>: 256 threads, A=fp16 single, B=fp16 hi/lo.
__global__ void k_mma64(const __half* __restrict__ Bh,
                        const __half* __restrict__ Bl,
                        float* __restrict__ C){
  constexpr int NO = 64;
  constexpr int BST = NO+8;
  __shared__ __half Ash[128*40];
  __shared__ __half Bsh[32*BST], Bsl[32*BST];
  int b = blockIdx.y;
  int m0 = blockIdx.x*128;
  int w = threadIdx.x>>5, lane = threadIdx.x&31;
  int wm = w*16;
  float acc[8][4];
  #pragma unroll
  for (int j=0;j<8;j++){ acc[j][0]=0.f; acc[j][1]=0.f; acc[j][2]=0.f; acc[j][3]=0.f; }
  const __half* Ahb = g_sh + (size_t)b*NNSQ;
  const __half* Bhb = Bh + (size_t)b*NN_*NO;
  const __half* Blb = Bl + (size_t)b*NN_*NO;
  for (int k0=0;k0<NN_;k0+=32){
    #pragma unroll
    for (int i = threadIdx.x; i<512; i+=256){
      int r = i>>2, c = i&3;
      *(uint4*)&Ash[r*40 + c*8] = *(const uint4*)&Ahb[(size_t)(m0+r)*NN_ + k0 + c*8];
    }
    {
      int i = threadIdx.x;
      int r = i>>3, c = i&7;
      *(uint4*)&Bsh[r*BST + c*8] = *(const uint4*)&Bhb[(size_t)(k0+r)*NO + c*8];
      *(uint4*)&Bsl[r*BST + c*8] = *(const uint4*)&Blb[(size_t)(k0+r)*NO + c*8];
    }
    __syncthreads();
    #pragma unroll
    for (int kk=0; kk<2; kk++){
      uint32_t ah[4];
      int aoff = (wm + (lane&15))*40 + kk*16 + (lane>>4)*8;
      ldsm4(ah[0],ah[1],ah[2],ah[3], &Ash[aoff]);
      #pragma unroll
      for (int j=0;j<8;j++){
        uint32_t bh[2], bl[2];
        int boff = (kk*16 + (lane&15))*BST + j*8;
        ldsm2t(bh[0],bh[1], &Bsh[boff]);
        ldsm2t(bl[0],bl[1], &Bsl[boff]);
        mma16816h(acc[j], ah, bh);
        mma16816h(acc[j], ah, bl);
      }
    }
    __syncthreads();
  }
  #pragma unroll
  for (int j=0;j<8;j++){
    int r0 = m0 + wm + (lane>>2);
    int c0 = j*8 + (lane&3)*2;
    float* Cp = C + ((size_t)b*NN_ + r0)*NO + c0;
    Cp[0] = acc[j][0]; Cp[1] = acc[j][1];
    Cp[(size_t)8*NO] = acc[j][2]; Cp[(size_t)8*NO+1] = acc[j][3];
  }
}

// r-gate: 4b x 4o register tile; W fp16; 4-way batched loads (MLP).
__global__ void __launch_bounds__(128) k_gate_r(const float* __restrict__ x,
                                                const float* __restrict__ st){
  int n = blockIdx.x;
  __shared__ float Xg[256*20];
  int t = threadIdx.x;
  for (int q=t; q<4096; q+=128){
    int b = q>>8, i = q&255;
    float v;
    if (i < 64)       v = x[((size_t)b*NN_+n)*64 + i];
    else if (i < 128) v = st[((size_t)b*NN_+n)*64 + (i-64)];
    else              v = g_xb[((size_t)b*NN_+n)*128 + (i-128)];
    Xg[i*20 + b] = v;
  }
  __syncthreads();
  int og = t>>2, bg = t&3;
  int o0 = og*4, b0 = bg*4;
  float acc[4][4] = {};
  const __half* W = g_Wn_r + (size_t)n*256*128 + o0;
  #pragma unroll 1
  for (int i=0;i<256;i+=4){
    uint2 wv[4]; float4 xv[4];
    #pragma unroll
    for (int u=0;u<4;u++){
      wv[u] = *(const uint2*)&W[(size_t)(i+u)*128];
      xv[u] = *(float4*)&Xg[(i+u)*20 + b0];
    }
    #pragma unroll
    for (int u=0;u<4;u++){
      float2 f01 = __half22float2(*(__half2*)&wv[u].x);
      float2 f23 = __half22float2(*(__half2*)&wv[u].y);
      float xs[4] = {xv[u].x,xv[u].y,xv[u].z,xv[u].w};
      float ws[4] = {f01.x,f01.y,f23.x,f23.y};
      #pragma unroll
      for (int bi=0;bi<4;bi++)
        #pragma unroll
        for (int oi=0;oi<4;oi++)
          acc[bi][oi] += xs[bi]*ws[oi];
    }
  }
  float4 bias = *(const float4*)&g_bias_r[n*128 + o0];
  float bs[4] = {bias.x,bias.y,bias.z,bias.w};
  #pragma unroll
  for (int bi=0;bi<4;bi++){
    int b = b0+bi;
    size_t idx = ((size_t)b*NN_+n)*64;
    #pragma unroll
    for (int oi=0;oi<4;oi++){
      int o = o0+oi;
      float g = 1.0f/(1.0f+__expf(-(acc[bi][oi]+bs[oi])));
      if (o < 64){
        float zsv = g * st[idx + o];
        g_zs[idx + o] = zsv;
        __half h, l; split_h16(zsv, h, l);
        g_zh[idx + o] = h; g_zl[idx + o] = l;
      } else {
        g_rb[idx + (o-64)] = g;
      }
    }
  }
}

// u-gate + GRU output; block 1024 computes mask_loss. W fp16; 4-way batched loads.
__global__ void __launch_bounds__(128) k_gate_u(const float* __restrict__ x,
                                                const float* __restrict__ st,
                                                float* __restrict__ out_h,
                                                float* __restrict__ out_loss){
  if (blockIdx.x == NN_){
    if (threadIdx.x < BB){
      unsigned int tot = 0;
      #pragma unroll
      for (int i=0;i<BB;i++) tot += g_pos[i];
      float active = (float)tot / (float)BNN;
      float addend = fmaxf(0.05f/active - 1.0f, 0.0f);
      int b = threadIdx.x;
      out_loss[b] = (float)g_kept[b] / ((float)g_pos[b] + 1e-8f) + addend;
    }
    return;
  }
  int n = blockIdx.x;
  __shared__ float Xg[256*20];
  int t = threadIdx.x;
  for (int q=t; q<4096; q+=128){
    int b = q>>8, i = q&255;
    float v;
    if (i < 64)       v = x[((size_t)b*NN_+n)*64 + i];
    else if (i < 128) v = g_zs[((size_t)b*NN_+n)*64 + (i-64)];
    else if (i < 192) v = g_xb[((size_t)b*NN_+n)*128 + (i-128)];
    else              v = g_c2[((size_t)b*NN_+n)*64 + (i-192)];
    Xg[i*20 + b] = v;
  }
  __syncthreads();
  int og = t>>3, bg = t&7;
  int o0 = og*4, b0 = bg*2;
  float acc[2][4] = {};
  const __half* W = g_Wn_u + (size_t)n*256*64 + o0;
  #pragma unroll 1
  for (int i=0;i<256;i+=4){
    uint2 wv[4]; float2 xv[4];
    #pragma unroll
    for (int u=0;u<4;u++){
      wv[u] = *(const uint2*)&W[(size_t)(i+u)*64];
      xv[u] = *(float2*)&Xg[(i+u)*20 + b0];
    }
    #pragma unroll
    for (int u=0;u<4;u++){
      float2 f01 = __half22float2(*(__half2*)&wv[u].x);
      float2 f23 = __half22float2(*(__half2*)&wv[u].y);
      float xs[2] = {xv[u].x,xv[u].y};
      float ws[4] = {f01.x,f01.y,f23.x,f23.y};
      #pragma unroll
      for (int bi=0;bi<2;bi++)
        #pragma unroll
        for (int oi=0;oi<4;oi++)
          acc[bi][oi] += xs[bi]*ws[oi];
    }
  }
  float4 bias = *(const float4*)&g_bias_u[n*64 + o0];
  float bs[4] = {bias.x,bias.y,bias.z,bias.w};
  #pragma unroll
  for (int bi=0;bi<2;bi++){
    int b = b0+bi;
    size_t idx = ((size_t)b*NN_+n)*64;
    #pragma unroll
    for (int oi=0;oi<4;oi++){
      int o = o0+oi;
      float hc = tanhf(acc[bi][oi]+bs[oi]);
      float r = g_rb[idx + o];
      float sv = st[idx + o];
      out_h[idx + o] = r*sv + (1.0f-r)*hc;
    }
  }
}

// ---------------- launch ----------------
extern "C" void kernel_launch(void* const* d_in, const int* in_sizes, int n_in,
                              void* d_out, int out_size){
  const float* x    = (const float*)d_in[0];
  const float* st   = (const float*)d_in[1];
  const float* we   = (const float*)d_in[2];
  const float* T    = (const float*)d_in[3];
  const float* Wpr  = (const float*)d_in[4];
  const float* bpr  = (const float*)d_in[5];
  const float* Wpu  = (const float*)d_in[6];
  const float* bpu  = (const float*)d_in[7];
  const float* mp   = (const float*)d_in[8];
  const float* tp   = (const float*)d_in[9];
  const float* gmm  = (const float*)d_in[10];
  const float* bta  = (const float*)d_in[11];
  const int*   itp  = (const int*)d_in[12];
  float* out = (float*)d_out;
  float* out_mask = out + OFF_MASK;

  static __half *xh_p=nullptr, *xl_p=nullptr, *zh_p=nullptr, *zl_p=nullptr;
  static float *xb_p=nullptr, *c2_p=nullptr;
  static cudaStream_t s2 = nullptr;
  static cudaEvent_t evF = nullptr, evS = nullptr, evW = nullptr, evJ = nullptr;
  if (!xh_p){
    cudaGetSymbolAddress((void**)&xh_p, g_xh);
    cudaGetSymbolAddress((void**)&xl_p, g_xl);
    cudaGetSymbolAddress((void**)&zh_p, g_zh);
    cudaGetSymbolAddress((void**)&zl_p, g_zl);
    cudaGetSymbolAddress((void**)&xb_p, g_xb);
    cudaGetSymbolAddress((void**)&c2_p, g_c2);
    size_t smem_sup = (size_t)(WINDOW*NN_)*sizeof(float);   // 48 KB
    cudaFuncSetAttribute(k_supmask, cudaFuncAttributeMaxDynamicSharedMemorySize, (int)smem_sup);
    cudaStreamCreateWithFlags(&s2, cudaStreamNonBlocking);
    cudaEventCreateWithFlags(&evF, cudaEventDisableTiming);
    cudaEventCreateWithFlags(&evS, cudaEventDisableTiming);
    cudaEventCreateWithFlags(&evW, cudaEventDisableTiming);
    cudaEventCreateWithFlags(&evJ, cudaEventDisableTiming);
  }
  size_t smem_sup = (size_t)(WINDOW*NN_)*sizeof(float);

  k_setup<<<64,256>>>(we, itp);                            // L1 (main)
  cudaEventRecord(evF, 0);
  k_pre<<<2048,256>>>(mp, bpr, bpu);                       // L2 (main)
  k_prep<<<2048,256>>>(x, st);                             // L3 (main)
  k_supmask<<<1024,256,smem_sup>>>(T, tp, gmm, bta, out_mask); // L4 (profiled)
  cudaEventRecord(evS, 0);
  // s2: wgen overlaps pre/prep/supmask; kept overlaps mma/gate chain
  cudaStreamWaitEvent(s2, evF, 0);
  k_wgen<<<512,256,0,s2>>>(Wpr, Wpu);                      // L5 (s2)
  cudaEventRecord(evW, s2);
  cudaStreamWaitEvent(s2, evS, 0);
  k_kept<<<8192,256,0,s2>>>();                             // L6 (s2)
  cudaEventRecord(evJ, s2);
  // main chain
  k_mma128<<<128,512>>>(xh_p, xl_p, xb_p);                 // L7 (main)
  cudaStreamWaitEvent(0, evW, 0);
  k_gate_r<<<NN_,128>>>(x, st);                            // L8 (main)
  k_mma64<<<dim3(8,16),256>>>(zh_p, zl_p, c2_p);           // L9 (main)
  cudaStreamWaitEvent(0, evJ, 0);
  k_gate_u<<<NN_+1,128>>>(x, st, out, out + OFF_LOSS);     // L10 (main)
}

// round 14
// speedup vs baseline: 1.0178x; 1.0178x over previous
#include <cuda_runtime.h>
#include <cuda_bf16.h>
#include <cuda_fp16.h>
#include <cstdint>
#include <math.h>

#define BB 16
#define NN_ 1024
#define EDIM 16
#define WINDOW 12
#define NNSQ (NN_*NN_)
#define BNN (BB*NNSQ)
#define HALF_BNN (BNN/2)
#define OFF_MASK (BB*NN_*64)
#define OFF_LOSS (OFF_MASK + BNN)
#define MASK_THR (-2.66352776f)   /* ln(1.4) - 3 */

// ---------------- scratch ----------------
__device__ float g_E[NN_*EDIM];
__device__ float g_Et[EDIM*NN_];
__device__ float g_EM[NNSQ];
__device__ float g_supports[NNSQ];
__device__ __half g_sh[(size_t)BNN];
__device__ uint32_t g_bits[BNN/32];
__device__ __half g_xh[(size_t)BB*NN_*128];
__device__ __half g_xl[(size_t)BB*NN_*128];
__device__ __half g_zh[(size_t)BB*NN_*64];
__device__ __half g_zl[(size_t)BB*NN_*64];
__device__ __half g_Wn_r[(size_t)NN_*256*128];
__device__ __half g_Wn_u[(size_t)NN_*256*64];
__device__ float g_bias_r[NN_*128];
__device__ float g_bias_u[NN_*64];
__device__ float g_xb[(size_t)BB*NN_*128];
__device__ float g_zs[(size_t)BB*NN_*64];
__device__ float g_rb[(size_t)BB*NN_*64];
__device__ float g_c2[(size_t)BB*NN_*64];
__device__ unsigned int g_pos[BB];
__device__ unsigned int g_kept[BB];

// ---------------- helpers ----------------
__device__ __forceinline__ float warpSum(float v){
  #pragma unroll
  for (int o=16;o;o>>=1) v += __shfl_xor_sync(0xffffffffu, v, o);
  return v;
}
__device__ __forceinline__ float blockSum(float v, float* red){
  int lane = threadIdx.x & 31, w = threadIdx.x >> 5;
  int nw = blockDim.x >> 5;
  v = warpSum(v);
  __syncthreads();
  if (lane==0) red[w] = v;
  __syncthreads();
  float r = (threadIdx.x < (unsigned)nw) ? red[threadIdx.x] : 0.0f;
  if (w==0) r = warpSum(r);
  if (threadIdx.x==0) red[0] = r;
  __syncthreads();
  return red[0];
}
__device__ __forceinline__ uint32_t rotl32(uint32_t x, int r){
  return __funnelshift_l(x, x, r);
}
__device__ __forceinline__ void threefry2x32(uint32_t k0, uint32_t k1,
                                             uint32_t& x0, uint32_t& x1){
  uint32_t ks0 = k0, ks1 = k1, ks2 = k0 ^ k1 ^ 0x1BD11BDAu;
  x0 += ks0; x1 += ks1;
  const int R0[4] = {13,15,26,6};
  const int R1[4] = {17,29,16,24};
  uint32_t ks[3] = {ks0, ks1, ks2};
  #pragma unroll
  for (int i=0;i<5;i++){
    #pragma unroll
    for (int j=0;j<4;j++){
      int r = (i & 1) ? R1[j] : R0[j];
      x0 += x1; x1 = rotl32(x1, r); x1 ^= x0;
    }
    x0 += ks[(i+1)%3];
    x1 += ks[(i+2)%3] + (uint32_t)(i+1);
  }
}
__device__ __forceinline__ void split_h16(float v, __half& h, __half& l){
  h = __float2half_rn(v);
  l = __float2half_rn(v - __half2float(h));
}
__device__ __forceinline__ uint32_t pack_h2(__half a, __half b){
  __half2 p(a, b);
  return *reinterpret_cast<uint32_t*>(&p);
}
__device__ __forceinline__ void ldsm4(uint32_t& r0,uint32_t& r1,uint32_t& r2,uint32_t& r3,
                                      const __half* p){
  uint32_t a = (uint32_t)__cvta_generic_to_shared(p);
  asm volatile("ldmatrix.sync.aligned.m8n8.x4.shared.b16 {%0,%1,%2,%3},[%4];"
    : "=r"(r0),"=r"(r1),"=r"(r2),"=r"(r3) : "r"(a));
}
__device__ __forceinline__ void ldsm2t(uint32_t& r0,uint32_t& r1, const __half* p){
  uint32_t a = (uint32_t)__cvta_generic_to_shared(p);
  asm volatile("ldmatrix.sync.aligned.m8n8.x2.trans.shared.b16 {%0,%1},[%2];"
    : "=r"(r0),"=r"(r1) : "r"(a));
}
__device__ __forceinline__ void mma16816h(float* c, const uint32_t* a, const uint32_t* b){
  asm volatile("mma.sync.aligned.m16n8k16.row.col.f32.f16.f16.f32 "
    "{%0,%1,%2,%3},{%4,%5,%6,%7},{%8,%9},{%0,%1,%2,%3};"
    : "+f"(c[0]),"+f"(c[1]),"+f"(c[2]),"+f"(c[3])
    : "r"(a[0]),"r"(a[1]),"r"(a[2]),"r"(a[3]), "r"(b[0]),"r"(b[1]));
}
__device__ __forceinline__ float prob_from_pos(){
  unsigned int tot = 0;
  #pragma unroll
  for (int i=0;i<BB;i++) tot += g_pos[i];
  float active = (float)tot / (float)BNN;
  return fminf(0.05f/active + 1e-8f, 1.0f);
}

// ---------------- kernels ----------------

__global__ void k_setup(const float* __restrict__ we, const int* __restrict__ itp){
  int tid = blockIdx.x*blockDim.x + threadIdx.x;
  float it = (float)itp[0];
  if (tid < NN_*EDIM){
    int d = tid & 15;
    int pair = d >> 1;
    float arg = (float)((double)(2*pair) * (-9.210340371976184/16.0));
    float div = expf(arg);
    float pe = (d & 1) ? cosf(it*div) : sinf(it*div);
    float e = we[tid] + pe;
    g_E[tid] = e;
    g_Et[d*NN_ + (tid>>4)] = e;
  }
  if (blockIdx.x==0 && threadIdx.x < 2*BB){
    if (threadIdx.x < BB) g_pos[threadIdx.x] = 0u;
    else                  g_kept[threadIdx.x-BB] = 0u;
  }
}

// [0,1024) em+bias, [1024,2048) supports.
__global__ void k_pre(const float* __restrict__ mp,
                      const float* __restrict__ bpr, const float* __restrict__ bpu){
  int g = blockIdx.x;
  if (g < NN_){
    int n = g;
    __shared__ float en[EDIM];
    if (threadIdx.x < EDIM) en[threadIdx.x] = g_E[n*EDIM+threadIdx.x];
    __syncthreads();
    int m0 = threadIdx.x*4;
    float4 a = make_float4(0.f,0.f,0.f,0.f);
    #pragma unroll
    for (int d=0; d<EDIM; d++){
      float4 mv = *(const float4*)&mp[d*NN_+m0];
      float e = en[d];
      a.x += e*mv.x; a.y += e*mv.y; a.z += e*mv.z; a.w += e*mv.w;
    }
    *(float4*)&g_EM[n*NN_+m0] = a;
    int o = threadIdx.x;
    if (o < 128){
      float br = 0.f;
      #pragma unroll
      for (int d=0; d<EDIM; d++) br += en[d]*bpr[d*128+o];
      g_bias_r[n*128+o] = br;
      if (o < 64){
        float bu = 0.f;
        #pragma unroll
        for (int d=0; d<EDIM; d++) bu += en[d]*bpu[d*64+o];
        g_bias_u[n*64+o] = bu;
      }
    }
  } else {
    int n = g - NN_;
    __shared__ float row[NN_];
    __shared__ float red[32];
    float en[EDIM];
    #pragma unroll
    for (int d=0; d<EDIM; d++) en[d] = g_E[n*EDIM+d];
    int m0 = threadIdx.x*4;
    float4 a = make_float4(0.f,0.f,0.f,0.f);
    #pragma unroll
    for (int d=0; d<EDIM; d++){
      float4 ev = *(const float4*)&g_Et[d*NN_+m0];
      float e = en[d];
      a.x += e*ev.x; a.y += e*ev.y; a.z += e*ev.z; a.w += e*ev.w;
    }
    a.x = __expf(fmaxf(a.x,0.f)); a.y = __expf(fmaxf(a.y,0.f));
    a.z = __expf(fmaxf(a.z,0.f)); a.w = __expf(fmaxf(a.w,0.f));
    *(float4*)&row[m0] = a;
    float s = blockSum(a.x+a.y+a.z+a.w, red);
    float inv = 1.0f/s;
    float4 r4 = *(float4*)&row[m0];
    r4.x *= inv; r4.y *= inv; r4.z *= inv; r4.w *= inv;
    *(float4*)&g_supports[n*NN_+m0] = r4;
  }
}

// prep: cat(x,state) -> fp16 hi/lo
__global__ void k_prep(const float* __restrict__ x, const float* __restrict__ st){
  int q = blockIdx.x*256 + threadIdx.x;
  int t4 = q*4;
  int j = t4 & 127; int bn = t4 >> 7;
  float4 v = (j < 64) ? *(const float4*)&x[(size_t)bn*64 + j]
                      : *(const float4*)&st[(size_t)bn*64 + (j-64)];
  __half h0,l0,h1,l1,h2,l2,h3,l3;
  split_h16(v.x,h0,l0); split_h16(v.y,h1,l1);
  split_h16(v.z,h2,l2); split_h16(v.w,h3,l3);
  *(uint2*)&g_xh[t4] = make_uint2(pack_h2(h0,h1), pack_h2(h2,h3));
  *(uint2*)&g_xl[t4] = make_uint2(pack_h2(l0,l1), pack_h2(l2,l3));
}

// Wn body with float2 register cache (reg-light for merged kernel).
template<int OC>
__device__ __forceinline__ void wgen_body(const float* __restrict__ Wp, __half* __restrict__ Wn,
                                          int lb, float* Esm){
  constexpr int NQ = OC/2;          // 64 or 32
  constexpr int NI = 256/NQ;        // 4 or 8
  int n0 = (lb>>4)*64;
  int i20 = (lb&15)*16;
  int t = threadIdx.x;
  int oq = t % NQ, ig = t / NQ;
  for (int q=t; q<64*EDIM; q+=256)
    Esm[q] = g_E[(n0 + (q>>4))*EDIM + (q&15)];
  __syncthreads();
  for (int ii=ig; ii<16; ii+=NI){
    int i2 = i20+ii;
    float2 w[EDIM];
    #pragma unroll
    for (int d=0; d<EDIM; d++)
      w[d] = *(const float2*)&Wp[((size_t)d*256 + i2)*OC + oq*2];
    #pragma unroll 4
    for (int nn=0; nn<64; nn++){
      float ax = 0.f, ay = 0.f;
      #pragma unroll
      for (int d=0; d<EDIM; d++){
        float e = Esm[nn*EDIM + d];
        ax += e*w[d].x; ay += e*w[d].y;
      }
      __half2 h01 = __floats2half2_rn(ax, ay);
      *(uint32_t*)&Wn[((size_t)(n0+nn)*256 + i2)*OC + oq*2] = *(uint32_t*)&h01;
    }
  }
}

// Merged: every 3rd block wgen (512), rest supmask (1024 blocks x 16 rows).
// launch_bounds(256,3) caps regs at 85 -> 3 blocks/SM (occ 1.5x vs R12).
__global__ void __launch_bounds__(256,3) k_sup_wgen(
    const float* __restrict__ T, const float* __restrict__ TP,
    const float* __restrict__ gamma, const float* __restrict__ beta,
    float* __restrict__ out_mask,
    const float* __restrict__ Wpr, const float* __restrict__ Wpu){
  __shared__ float red[8][8];
  __shared__ float inv8[8];
  extern __shared__ float sm[];
  float* Tsm = sm;                          // 48 KB (wgen blocks reuse as Esm)
  int bid = blockIdx.x;
  if (bid % 3 == 0){
    int lb = bid/3;
    if (lb < 256) wgen_body<128>(Wpr, g_Wn_r, lb, Tsm);
    else          wgen_body<64>(Wpu, g_Wn_u, lb-256, Tsm);
    return;
  }
  int id = bid - bid/3 - 1;                 // [0,1024)
  int b = id >> 6;
  int n0base = (id & 63)*16;
  int tid = threadIdx.x, lane = tid & 31, wrp = tid >> 5;
  {
    const float4* Tg = (const float4*)(T + (size_t)b*WINDOW*NN_);
    float4* T4 = (float4*)Tsm;
    #pragma unroll
    for (int i=0;i<12;i++) T4[tid + i*256] = Tg[tid + i*256];
  }
  __syncthreads();
  int m0 = tid*4;
  const float bni = 1.0f/sqrtf(1.0f + 1e-5f);
  unsigned int cnt = 0;
  #pragma unroll 1
  for (int half=0; half<2; half++){
    int n0 = n0base + half*8;
    float tg[8][4];
    #pragma unroll
    for (int r=0;r<8;r++){ tg[r][0]=0.f; tg[r][1]=0.f; tg[r][2]=0.f; tg[r][3]=0.f; }
    #pragma unroll
    for (int w=0; w<WINDOW; w++){
      float4 tw = *(float4*)&Tsm[w*NN_+m0];
      #pragma unroll
      for (int r=0;r<8;r++){
        float tvs = Tsm[w*NN_ + n0 + r];
        tg[r][0] += tvs*tw.x; tg[r][1] += tvs*tw.y;
        tg[r][2] += tvs*tw.z; tg[r][3] += tvs*tw.w;
      }
    }
    float psum[8];
    #pragma unroll
    for (int r=0;r<8;r++){
      tg[r][0] = __expf(fmaxf(tg[r][0],0.f));
      tg[r][1] = __expf(fmaxf(tg[r][1],0.f));
      tg[r][2] = __expf(fmaxf(tg[r][2],0.f));
      tg[r][3] = __expf(fmaxf(tg[r][3],0.f));
      psum[r] = (tg[r][0]+tg[r][1])+(tg[r][2]+tg[r][3]);
    }
    #pragma unroll
    for (int r=0;r<8;r++) psum[r] = warpSum(psum[r]);
    __syncthreads();
    if (lane==0){
      #pragma unroll
      for (int r=0;r<8;r++) red[r][wrp] = psum[r];
    }
    __syncthreads();
    if (tid < 8){
      float s = 0.f;
      #pragma unroll
      for (int k=0;k<8;k++) s += red[tid][k];
      inv8[tid] = 1.0f/s;
    }
    __syncthreads();
    float rm[8][4];
    #pragma unroll
    for (int r=0;r<8;r++){
      float4 t = *(const float4*)&g_EM[(size_t)(n0+r)*NN_ + m0];
      rm[r][0]=t.x; rm[r][1]=t.y; rm[r][2]=t.z; rm[r][3]=t.w;
    }
    #pragma unroll
    for (int w=0; w<WINDOW; w++){
      float4 tp = __ldg((const float4*)&TP[w*NN_+m0]);
      #pragma unroll
      for (int r=0;r<8;r++){
        float tvs = Tsm[w*NN_ + n0 + r];
        rm[r][0] += tvs*tp.x; rm[r][1] += tvs*tp.y;
        rm[r][2] += tvs*tp.z; rm[r][3] += tvs*tp.w;
      }
    }
    #pragma unroll
    for (int r=0;r<8;r++){
      int n = n0 + r;
      float sc = bni*gamma[n], bt = beta[n];
      float v0 = rm[r][0]*sc + bt, v1 = rm[r][1]*sc + bt;
      float v2 = rm[r][2]*sc + bt, v3 = rm[r][3]*sc + bt;
      uint32_t nib = (v0 > MASK_THR ? 1u:0u) | (v1 > MASK_THR ? 2u:0u)
                   | (v2 > MASK_THR ? 4u:0u) | (v3 > MASK_THR ? 8u:0u);
      float4 mk = make_float4(nib&1u?1.f:0.f, nib&2u?1.f:0.f, nib&4u?1.f:0.f, nib&8u?1.f:0.f);
      size_t idx = (size_t)b*NNSQ + (size_t)n*NN_ + m0;
      *(float4*)&out_mask[idx] = mk;
      float inv = inv8[r];
      float4 sp = *(const float4*)&g_supports[n*NN_+m0];
      sp.x = (sp.x + tg[r][0]*inv)*0.5f*mk.x;
      sp.y = (sp.y + tg[r][1]*inv)*0.5f*mk.y;
      sp.z = (sp.z + tg[r][2]*inv)*0.5f*mk.z;
      sp.w = (sp.w + tg[r][3]*inv)*0.5f*mk.w;
      *(uint2*)&g_sh[idx] = make_uint2(
          pack_h2(__float2half_rn(sp.x), __float2half_rn(sp.y)),
          pack_h2(__float2half_rn(sp.z), __float2half_rn(sp.w)));
      cnt += __popc(nib);
      uint32_t v = nib << ((lane&7)*4);
      v |= __shfl_xor_sync(0xffffffffu, v, 1);
      v |= __shfl_xor_sync(0xffffffffu, v, 2);
      v |= __shfl_xor_sync(0xffffffffu, v, 4);
      if ((lane&7)==0) g_bits[idx>>5] = v;
    }
  }
  __syncthreads();
  float fc = blockSum((float)cnt, (float*)red);
  if (tid==0) atomicAdd(&g_pos[b], (unsigned int)(fc + 0.5f));
}

// kept-count: forked on s2 (proven overlap with mma/gate chain).
__global__ void __launch_bounds__(256) k_kept(){
  __shared__ unsigned int cnt[BB];
  if (threadIdx.x < BB) cnt[threadIdx.x] = 0u;
  __syncthreads();
  float prob = prob_from_pos();
  int lane = threadIdx.x & 31;
  unsigned int base = blockIdx.x*1024u + threadIdx.x;
  #pragma unroll
  for (int k=0;k<4;k++){
    unsigned int t = base + (unsigned)k*256u;
    uint32_t x0 = t, x1 = t + (uint32_t)HALF_BNN;
    threefry2x32(0u, 42u, x0, x1);
    float u0 = __uint_as_float((x0>>9) | 0x3f800000u) - 1.0f;
    float u1 = __uint_as_float((x1>>9) | 0x3f800000u) - 1.0f;
    uint32_t w0 = g_bits[t>>5];
    uint32_t w1 = g_bits[(t + HALF_BNN)>>5];
    int b0 = (int)(t >> 20);
    bool keep0 = ((w0>>lane)&1u) && !(u0 < prob);
    bool keep1 = ((w1>>lane)&1u) && !(u1 < prob);
    unsigned bal0 = __ballot_sync(0xffffffffu, keep0);
    unsigned bal1 = __ballot_sync(0xffffffffu, keep1);
    if (lane==0){
      if (bal0) atomicAdd(&cnt[b0],   __popc(bal0));
      if (bal1) atomicAdd(&cnt[b0+8], __popc(bal1));
    }
  }
  __syncthreads();
  if (threadIdx.x < BB && cnt[threadIdx.x]) atomicAdd(&g_kept[threadIdx.x], cnt[threadIdx.x]);
}

// mma<128>: 512 threads, A=fp16 sup, B=fp16 hi/lo; double-buffered + prefetch.
__global__ void __launch_bounds__(512) k_mma128(const __half* __restrict__ Bh,
                                                const __half* __restrict__ Bl,
                                                float* __restrict__ C){
  constexpr int NO = 128;
  constexpr int BST = NO+8;
  constexpr int APITCH = 40;
  __shared__ __half Ash[2][128*APITCH];
  __shared__ __half Bsh[2][32*BST], Bsl[2][32*BST];
  int b = blockIdx.x >> 3;
  int m0 = (blockIdx.x & 7)*128;
  int w = threadIdx.x>>5, lane = threadIdx.x&31;
  int wm = (w>>1)*16;
  int wn = (w&1)*64;
  float acc[8][4];
  #pragma unroll
  for (int j=0;j<8;j++){ acc[j][0]=0.f; acc[j][1]=0.f; acc[j][2]=0.f; acc[j][3]=0.f; }
  const __half* Ahb = g_sh + (size_t)b*NNSQ;
  const __half* Bhb = Bh + (size_t)b*NN_*NO;
  const __half* Blb = Bl + (size_t)b*NN_*NO;
  int ar = threadIdx.x>>2, ac = threadIdx.x&3;
  int brr = threadIdx.x>>4, bc = threadIdx.x&15;
  uint4 pAh, pBh, pBl;
  auto ldtile = [&](int k0){
    pAh = *(const uint4*)&Ahb[(size_t)(m0+ar)*NN_ + k0 + ac*8];
    pBh = *(const uint4*)&Bhb[(size_t)(k0+brr)*NO + bc*8];
    pBl = *(const uint4*)&Blb[(size_t)(k0+brr)*NO + bc*8];
  };
  auto sttile = [&](int buf){
    *(uint4*)&Ash[buf][ar*APITCH + ac*8] = pAh;
    *(uint4*)&Bsh[buf][brr*BST + bc*8] = pBh;
    *(uint4*)&Bsl[buf][brr*BST + bc*8] = pBl;
  };
  ldtile(0);
  sttile(0);
  __syncthreads();
  #pragma unroll 1
  for (int t=0;t<32;t++){
    if (t+1 < 32) ldtile((t+1)*32);
    int buf = t & 1;
    #pragma unroll
    for (int kk=0; kk<2; kk++){
      uint32_t ah[4];
      int aoff = (wm + (lane&15))*APITCH + kk*16 + (lane>>4)*8;
      ldsm4(ah[0],ah[1],ah[2],ah[3], &Ash[buf][aoff]);
      #pragma unroll
      for (int j=0;j<8;j++){
        uint32_t bh[2], bl[2];
        int boff = (kk*16 + (lane&15))*BST + wn + j*8;
        ldsm2t(bh[0],bh[1], &Bsh[buf][boff]);
        ldsm2t(bl[0],bl[1], &Bsl[buf][boff]);
        mma16816h(acc[j], ah, bh);
        mma16816h(acc[j], ah, bl);
      }
    }
    if (t+1 < 32){
      __syncthreads();
      sttile((t+1)&1);
      __syncthreads();
    }
  }
  #pragma unroll
  for (int j=0;j<8;j++){
    int r0 = m0 + wm + (lane>>2);
    int c0 = wn + j*8 + (lane&3)*2;
    float* Cp = C + ((size_t)b*NN_ + r0)*NO + c0;
    Cp[0] = acc[j][0]; Cp[1] = acc[j][1];
    Cp[(size_t)8*NO] = acc[j][2]; Cp[(size_t)8*NO+1] = acc[j][3];
  }
}

// mma<64>: 256 threads, A=fp16 single, B=fp16 hi/lo.
__global__ void k_mma64(const __half* __restrict__ Bh,
                        const __half* __restrict__ Bl,
                        float* __restrict__ C){
  constexpr int NO = 64;
  constexpr int BST = NO+8;
  __shared__ __half Ash[128*40];
  __shared__ __half Bsh[32*BST], Bsl[32*BST];
  int b = blockIdx.y;
  int m0 = blockIdx.x*128;
  int w = threadIdx.x>>5, lane = threadIdx.x&31;
  int wm = w*16;
  float acc[8][4];
  #pragma unroll
  for (int j=0;j<8;j++){ acc[j][0]=0.f; acc[j][1]=0.f; acc[j][2]=0.f; acc[j][3]=0.f; }
  const __half* Ahb = g_sh + (size_t)b*NNSQ;
  const __half* Bhb = Bh + (size_t)b*NN_*NO;
  const __half* Blb = Bl + (size_t)b*NN_*NO;
  for (int k0=0;k0<NN_;k0+=32){
    #pragma unroll
    for (int i = threadIdx.x; i<512; i+=256){
      int r = i>>2, c = i&3;
      *(uint4*)&Ash[r*40 + c*8] = *(const uint4*)&Ahb[(size_t)(m0+r)*NN_ + k0 + c*8];
    }
    {
      int i = threadIdx.x;
      int r = i>>3, c = i&7;
      *(uint4*)&Bsh[r*BST + c*8] = *(const uint4*)&Bhb[(size_t)(k0+r)*NO + c*8];
      *(uint4*)&Bsl[r*BST + c*8] = *(const uint4*)&Blb[(size_t)(k0+r)*NO + c*8];
    }
    __syncthreads();
    #pragma unroll
    for (int kk=0; kk<2; kk++){
      uint32_t ah[4];
      int aoff = (wm + (lane&15))*40 + kk*16 + (lane>>4)*8;
      ldsm4(ah[0],ah[1],ah[2],ah[3], &Ash[aoff]);
      #pragma unroll
      for (int j=0;j<8;j++){
        uint32_t bh[2], bl[2];
        int boff = (kk*16 + (lane&15))*BST + j*8;
        ldsm2t(bh[0],bh[1], &Bsh[boff]);
        ldsm2t(bl[0],bl[1], &Bsl[boff]);
        mma16816h(acc[j], ah, bh);
        mma16816h(acc[j], ah, bl);
      }
    }
    __syncthreads();
  }
  #pragma unroll
  for (int j=0;j<8;j++){
    int r0 = m0 + wm + (lane>>2);
    int c0 = j*8 + (lane&3)*2;
    float* Cp = C + ((size_t)b*NN_ + r0)*NO + c0;
    Cp[0] = acc[j][0]; Cp[1] = acc[j][1];
    Cp[(size_t)8*NO] = acc[j][2]; Cp[(size_t)8*NO+1] = acc[j][3];
  }
}

// r-gate: 4b x 4o register tile; W fp16; 4-way batched loads.
__global__ void __launch_bounds__(128) k_gate_r(const float* __restrict__ x,
                                                const float* __restrict__ st){
  int n = blockIdx.x;
  __shared__ float Xg[256*20];
  int t = threadIdx.x;
  for (int q=t; q<4096; q+=128){
    int b = q>>8, i = q&255;
    float v;
    if (i < 64)       v = x[((size_t)b*NN_+n)*64 + i];
    else if (i < 128) v = st[((size_t)b*NN_+n)*64 + (i-64)];
    else              v = g_xb[((size_t)b*NN_+n)*128 + (i-128)];
    Xg[i*20 + b] = v;
  }
  __syncthreads();
  int og = t>>2, bg = t&3;
  int o0 = og*4, b0 = bg*4;
  float acc[4][4] = {};
  const __half* W = g_Wn_r + (size_t)n*256*128 + o0;
  #pragma unroll 1
  for (int i=0;i<256;i+=4){
    uint2 wv[4]; float4 xv[4];
    #pragma unroll
    for (int u=0;u<4;u++){
      wv[u] = *(const uint2*)&W[(size_t)(i+u)*128];
      xv[u] = *(float4*)&Xg[(i+u)*20 + b0];
    }
    #pragma unroll
    for (int u=0;u<4;u++){
      float2 f01 = __half22float2(*(__half2*)&wv[u].x);
      float2 f23 = __half22float2(*(__half2*)&wv[u].y);
      float xs[4] = {xv[u].x,xv[u].y,xv[u].z,xv[u].w};
      float ws[4] = {f01.x,f01.y,f23.x,f23.y};
      #pragma unroll
      for (int bi=0;bi<4;bi++)
        #pragma unroll
        for (int oi=0;oi<4;oi++)
          acc[bi][oi] += xs[bi]*ws[oi];
    }
  }
  float4 bias = *(const float4*)&g_bias_r[n*128 + o0];
  float bs[4] = {bias.x,bias.y,bias.z,bias.w};
  #pragma unroll
  for (int bi=0;bi<4;bi++){
    int b = b0+bi;
    size_t idx = ((size_t)b*NN_+n)*64;
    #pragma unroll
    for (int oi=0;oi<4;oi++){
      int o = o0+oi;
      float g = 1.0f/(1.0f+__expf(-(acc[bi][oi]+bs[oi])));
      if (o < 64){
        float zsv = g * st[idx + o];
        g_zs[idx + o] = zsv;
        __half h, l; split_h16(zsv, h, l);
        g_zh[idx + o] = h; g_zl[idx + o] = l;
      } else {
        g_rb[idx + (o-64)] = g;
      }
    }
  }
}

// u-gate + GRU output; block 1024 computes mask_loss. W fp16; 4-way batched loads.
__global__ void __launch_bounds__(128) k_gate_u(const float* __restrict__ x,
                                                const float* __restrict__ st,
                                                float* __restrict__ out_h,
                                                float* __restrict__ out_loss){
  if (blockIdx.x == NN_){
    if (threadIdx.x < BB){
      unsigned int tot = 0;
      #pragma unroll
      for (int i=0;i<BB;i++) tot += g_pos[i];
      float active = (float)tot / (float)BNN;
      float addend = fmaxf(0.05f/active - 1.0f, 0.0f);
      int b = threadIdx.x;
      out_loss[b] = (float)g_kept[b] / ((float)g_pos[b] + 1e-8f) + addend;
    }
    return;
  }
  int n = blockIdx.x;
  __shared__ float Xg[256*20];
  int t = threadIdx.x;
  for (int q=t; q<4096; q+=128){
    int b = q>>8, i = q&255;
    float v;
    if (i < 64)       v = x[((size_t)b*NN_+n)*64 + i];
    else if (i < 128) v = g_zs[((size_t)b*NN_+n)*64 + (i-64)];
    else if (i < 192) v = g_xb[((size_t)b*NN_+n)*128 + (i-128)];
    else              v = g_c2[((size_t)b*NN_+n)*64 + (i-192)];
    Xg[i*20 + b] = v;
  }
  __syncthreads();
  int og = t>>3, bg = t&7;
  int o0 = og*4, b0 = bg*2;
  float acc[2][4] = {};
  const __half* W = g_Wn_u + (size_t)n*256*64 + o0;
  #pragma unroll 1
  for (int i=0;i<256;i+=4){
    uint2 wv[4]; float2 xv[4];
    #pragma unroll
    for (int u=0;u<4;u++){
      wv[u] = *(const uint2*)&W[(size_t)(i+u)*64];
      xv[u] = *(float2*)&Xg[(i+u)*20 + b0];
    }
    #pragma unroll
    for (int u=0;u<4;u++){
      float2 f01 = __half22float2(*(__half2*)&wv[u].x);
      float2 f23 = __half22float2(*(__half2*)&wv[u].y);
      float xs[2] = {xv[u].x,xv[u].y};
      float ws[4] = {f01.x,f01.y,f23.x,f23.y};
      #pragma unroll
      for (int bi=0;bi<2;bi++)
        #pragma unroll
        for (int oi=0;oi<4;oi++)
          acc[bi][oi] += xs[bi]*ws[oi];
    }
  }
  float4 bias = *(const float4*)&g_bias_u[n*64 + o0];
  float bs[4] = {bias.x,bias.y,bias.z,bias.w};
  #pragma unroll
  for (int bi=0;bi<2;bi++){
    int b = b0+bi;
    size_t idx = ((size_t)b*NN_+n)*64;
    #pragma unroll
    for (int oi=0;oi<4;oi++){
      int o = o0+oi;
      float hc = tanhf(acc[bi][oi]+bs[oi]);
      float r = g_rb[idx + o];
      float sv = st[idx + o];
      out_h[idx + o] = r*sv + (1.0f-r)*hc;
    }
  }
}

// ---------------- launch ----------------
extern "C" void kernel_launch(void* const* d_in, const int* in_sizes, int n_in,
                              void* d_out, int out_size){
  const float* x    = (const float*)d_in[0];
  const float* st   = (const float*)d_in[1];
  const float* we   = (const float*)d_in[2];
  const float* T    = (const float*)d_in[3];
  const float* Wpr  = (const float*)d_in[4];
  const float* bpr  = (const float*)d_in[5];
  const float* Wpu  = (const float*)d_in[6];
  const float* bpu  = (const float*)d_in[7];
  const float* mp   = (const float*)d_in[8];
  const float* tp   = (const float*)d_in[9];
  const float* gmm  = (const float*)d_in[10];
  const float* bta  = (const float*)d_in[11];
  const int*   itp  = (const int*)d_in[12];
  float* out = (float*)d_out;
  float* out_mask = out + OFF_MASK;

  static __half *xh_p=nullptr, *xl_p=nullptr, *zh_p=nullptr, *zl_p=nullptr;
  static float *xb_p=nullptr, *c2_p=nullptr;
  static cudaStream_t s2 = nullptr;
  static cudaEvent_t evFork = nullptr, evJoin = nullptr;
  if (!xh_p){
    cudaGetSymbolAddress((void**)&xh_p, g_xh);
    cudaGetSymbolAddress((void**)&xl_p, g_xl);
    cudaGetSymbolAddress((void**)&zh_p, g_zh);
    cudaGetSymbolAddress((void**)&zl_p, g_zl);
    cudaGetSymbolAddress((void**)&xb_p, g_xb);
    cudaGetSymbolAddress((void**)&c2_p, g_c2);
    size_t smem_sup = (size_t)(WINDOW*NN_)*sizeof(float);   // 48 KB
    cudaFuncSetAttribute(k_sup_wgen, cudaFuncAttributeMaxDynamicSharedMemorySize, (int)smem_sup);
    cudaStreamCreateWithFlags(&s2, cudaStreamNonBlocking);
    cudaEventCreateWithFlags(&evFork, cudaEventDisableTiming);
    cudaEventCreateWithFlags(&evJoin, cudaEventDisableTiming);
  }
  size_t smem_sup = (size_t)(WINDOW*NN_)*sizeof(float);

  k_setup<<<64,256>>>(we, itp);                            // L1
  k_pre<<<2048,256>>>(mp, bpr, bpu);                       // L2
  k_prep<<<2048,256>>>(x, st);                             // L3
  k_sup_wgen<<<1536,256,smem_sup>>>(T, tp, gmm, bta, out_mask, Wpr, Wpu); // L4 (profiled)
  cudaEventRecord(evFork, 0);
  cudaStreamWaitEvent(s2, evFork, 0);
  k_kept<<<8192,256,0,s2>>>();
  k_mma128<<<128,512>>>(xh_p, xl_p, xb_p);
  k_gate_r<<<NN_,128>>>(x, st);
  k_mma64<<<dim3(8,16),256>>>(zh_p, zl_p, c2_p);
  cudaEventRecord(evJoin, s2);
  cudaStreamWaitEvent(0, evJoin, 0);
  k_gate_u<<<NN_+1,128>>>(x, st, out, out + OFF_LOSS);
}

// round 17
// speedup vs baseline: 1.0274x; 1.0095x over previous
#include <cuda_runtime.h>
#include <cuda_bf16.h>
#include <cuda_fp16.h>
#include <cstdint>
#include <math.h>

#define BB 16
#define NN_ 1024
#define EDIM 16
#define WINDOW 12
#define NNSQ (NN_*NN_)
#define BNN (BB*NNSQ)
#define HALF_BNN (BNN/2)
#define OFF_MASK (BB*NN_*64)
#define OFF_LOSS (OFF_MASK + BNN)
#define MASK_THR (-2.66352776f)   /* ln(1.4) - 3 */

// ---------------- scratch ----------------
__device__ float g_E[NN_*EDIM];
__device__ float g_Et[EDIM*NN_];
__device__ float g_EM[NNSQ];
__device__ float g_supports[NNSQ];
__device__ __half g_sh[(size_t)BNN];
__device__ uint32_t g_bits[BNN/32];
__device__ __half g_xh[(size_t)BB*NN_*128];
__device__ __half g_xl[(size_t)BB*NN_*128];
__device__ __half g_zh[(size_t)BB*NN_*64];
__device__ __half g_zl[(size_t)BB*NN_*64];
__device__ __half g_Wn_r[(size_t)NN_*256*128];
__device__ __half g_Wn_u[(size_t)NN_*256*64];
__device__ float g_bias_r[NN_*128];
__device__ float g_bias_u[NN_*64];
__device__ float g_xb[(size_t)BB*NN_*128];
__device__ float g_zs[(size_t)BB*NN_*64];
__device__ float g_rb[(size_t)BB*NN_*64];
__device__ float g_c2[(size_t)BB*NN_*64];
__device__ unsigned int g_pos[BB];
__device__ unsigned int g_kept[BB];

// ---------------- helpers ----------------
__device__ __forceinline__ float warpSum(float v){
  #pragma unroll
  for (int o=16;o;o>>=1) v += __shfl_xor_sync(0xffffffffu, v, o);
  return v;
}
__device__ __forceinline__ float blockSum(float v, float* red){
  int lane = threadIdx.x & 31, w = threadIdx.x >> 5;
  int nw = blockDim.x >> 5;
  v = warpSum(v);
  __syncthreads();
  if (lane==0) red[w] = v;
  __syncthreads();
  float r = (threadIdx.x < (unsigned)nw) ? red[threadIdx.x] : 0.0f;
  if (w==0) r = warpSum(r);
  if (threadIdx.x==0) red[0] = r;
  __syncthreads();
  return red[0];
}
__device__ __forceinline__ uint32_t rotl32(uint32_t x, int r){
  return __funnelshift_l(x, x, r);
}
__device__ __forceinline__ void threefry2x32(uint32_t k0, uint32_t k1,
                                             uint32_t& x0, uint32_t& x1){
  uint32_t ks0 = k0, ks1 = k1, ks2 = k0 ^ k1 ^ 0x1BD11BDAu;
  x0 += ks0; x1 += ks1;
  const int R0[4] = {13,15,26,6};
  const int R1[4] = {17,29,16,24};
  uint32_t ks[3] = {ks0, ks1, ks2};
  #pragma unroll
  for (int i=0;i<5;i++){
    #pragma unroll
    for (int j=0;j<4;j++){
      int r = (i & 1) ? R1[j] : R0[j];
      x0 += x1; x1 = rotl32(x1, r); x1 ^= x0;
    }
    x0 += ks[(i+1)%3];
    x1 += ks[(i+2)%3] + (uint32_t)(i+1);
  }
}
__device__ __forceinline__ void split_h16(float v, __half& h, __half& l){
  h = __float2half_rn(v);
  l = __float2half_rn(v - __half2float(h));
}
__device__ __forceinline__ uint32_t pack_h2(__half a, __half b){
  __half2 p(a, b);
  return *reinterpret_cast<uint32_t*>(&p);
}
__device__ __forceinline__ void ldsm4(uint32_t& r0,uint32_t& r1,uint32_t& r2,uint32_t& r3,
                                      const __half* p){
  uint32_t a = (uint32_t)__cvta_generic_to_shared(p);
  asm volatile("ldmatrix.sync.aligned.m8n8.x4.shared.b16 {%0,%1,%2,%3},[%4];"
    : "=r"(r0),"=r"(r1),"=r"(r2),"=r"(r3) : "r"(a));
}
__device__ __forceinline__ void ldsm2t(uint32_t& r0,uint32_t& r1, const __half* p){
  uint32_t a = (uint32_t)__cvta_generic_to_shared(p);
  asm volatile("ldmatrix.sync.aligned.m8n8.x2.trans.shared.b16 {%0,%1},[%2];"
    : "=r"(r0),"=r"(r1) : "r"(a));
}
__device__ __forceinline__ void mma16816h(float* c, const uint32_t* a, const uint32_t* b){
  asm volatile("mma.sync.aligned.m16n8k16.row.col.f32.f16.f16.f32 "
    "{%0,%1,%2,%3},{%4,%5,%6,%7},{%8,%9},{%0,%1,%2,%3};"
    : "+f"(c[0]),"+f"(c[1]),"+f"(c[2]),"+f"(c[3])
    : "r"(a[0]),"r"(a[1]),"r"(a[2]),"r"(a[3]), "r"(b[0]),"r"(b[1]));
}
__device__ __forceinline__ float prob_from_pos(){
  unsigned int tot = 0;
  #pragma unroll
  for (int i=0;i<BB;i++) tot += g_pos[i];
  float active = (float)tot / (float)BNN;
  return fminf(0.05f/active + 1e-8f, 1.0f);
}

// ---------------- kernels ----------------

__global__ void k_setup(const float* __restrict__ we, const int* __restrict__ itp){
  int tid = blockIdx.x*blockDim.x + threadIdx.x;
  float it = (float)itp[0];
  if (tid < NN_*EDIM){
    int d = tid & 15;
    int pair = d >> 1;
    float arg = (float)((double)(2*pair) * (-9.210340371976184/16.0));
    float div = expf(arg);
    float pe = (d & 1) ? cosf(it*div) : sinf(it*div);
    float e = we[tid] + pe;
    g_E[tid] = e;
    g_Et[d*NN_ + (tid>>4)] = e;
  }
  if (blockIdx.x==0 && threadIdx.x < 2*BB){
    if (threadIdx.x < BB) g_pos[threadIdx.x] = 0u;
    else                  g_kept[threadIdx.x-BB] = 0u;
  }
}

// [0,1024) em+bias, [1024,2048) supports.
__global__ void k_pre(const float* __restrict__ mp,
                      const float* __restrict__ bpr, const float* __restrict__ bpu){
  int g = blockIdx.x;
  if (g < NN_){
    int n = g;
    __shared__ float en[EDIM];
    if (threadIdx.x < EDIM) en[threadIdx.x] = g_E[n*EDIM+threadIdx.x];
    __syncthreads();
    int m0 = threadIdx.x*4;
    float4 a = make_float4(0.f,0.f,0.f,0.f);
    #pragma unroll
    for (int d=0; d<EDIM; d++){
      float4 mv = *(const float4*)&mp[d*NN_+m0];
      float e = en[d];
      a.x += e*mv.x; a.y += e*mv.y; a.z += e*mv.z; a.w += e*mv.w;
    }
    *(float4*)&g_EM[n*NN_+m0] = a;
    int o = threadIdx.x;
    if (o < 128){
      float br = 0.f;
      #pragma unroll
      for (int d=0; d<EDIM; d++) br += en[d]*bpr[d*128+o];
      g_bias_r[n*128+o] = br;
      if (o < 64){
        float bu = 0.f;
        #pragma unroll
        for (int d=0; d<EDIM; d++) bu += en[d]*bpu[d*64+o];
        g_bias_u[n*64+o] = bu;
      }
    }
  } else {
    int n = g - NN_;
    __shared__ float row[NN_];
    __shared__ float red[32];
    float en[EDIM];
    #pragma unroll
    for (int d=0; d<EDIM; d++) en[d] = g_E[n*EDIM+d];
    int m0 = threadIdx.x*4;
    float4 a = make_float4(0.f,0.f,0.f,0.f);
    #pragma unroll
    for (int d=0; d<EDIM; d++){
      float4 ev = *(const float4*)&g_Et[d*NN_+m0];
      float e = en[d];
      a.x += e*ev.x; a.y += e*ev.y; a.z += e*ev.z; a.w += e*ev.w;
    }
    a.x = __expf(fmaxf(a.x,0.f)); a.y = __expf(fmaxf(a.y,0.f));
    a.z = __expf(fmaxf(a.z,0.f)); a.w = __expf(fmaxf(a.w,0.f));
    *(float4*)&row[m0] = a;
    float s = blockSum(a.x+a.y+a.z+a.w, red);
    float inv = 1.0f/s;
    float4 r4 = *(float4*)&row[m0];
    r4.x *= inv; r4.y *= inv; r4.z *= inv; r4.w *= inv;
    *(float4*)&g_supports[n*NN_+m0] = r4;
  }
}

// prep: cat(x,state) -> fp16 hi/lo (on s2 after fork event)
__global__ void k_prep(const float* __restrict__ x, const float* __restrict__ st){
  int q = blockIdx.x*256 + threadIdx.x;
  int t4 = q*4;
  int j = t4 & 127; int bn = t4 >> 7;
  float4 v = (j < 64) ? *(const float4*)&x[(size_t)bn*64 + j]
                      : *(const float4*)&st[(size_t)bn*64 + (j-64)];
  __half h0,l0,h1,l1,h2,l2,h3,l3;
  split_h16(v.x,h0,l0); split_h16(v.y,h1,l1);
  split_h16(v.z,h2,l2); split_h16(v.w,h3,l3);
  *(uint2*)&g_xh[t4] = make_uint2(pack_h2(h0,h1), pack_h2(h2,h3));
  *(uint2*)&g_xl[t4] = make_uint2(pack_h2(l0,l1), pack_h2(l2,l3));
}

// Wn[n,i2,o] = sum_d E[n,d] * Wp[d,i2,o] -> fp16 (R12 float4 body)
template<int OC>
__device__ __forceinline__ void wgen_body(const float* __restrict__ Wp, __half* __restrict__ Wn,
                                          int lb, float* Esm){
  constexpr int NQ = OC/4;
  constexpr int NI = 256/NQ;
  int n0 = (lb>>4)*64;
  int i20 = (lb&15)*16;
  int t = threadIdx.x;
  int oq = t % NQ, ig = t / NQ;
  for (int q=t; q<64*EDIM; q+=256)
    Esm[q] = g_E[(n0 + (q>>4))*EDIM + (q&15)];
  __syncthreads();
  for (int ii=ig; ii<16; ii+=NI){
    int i2 = i20+ii;
    float4 w[EDIM];
    #pragma unroll
    for (int d=0; d<EDIM; d++)
      w[d] = *(const float4*)&Wp[((size_t)d*256 + i2)*OC + oq*4];
    #pragma unroll 4
    for (int nn=0; nn<64; nn++){
      float4 a = make_float4(0.f,0.f,0.f,0.f);
      #pragma unroll
      for (int d=0; d<EDIM; d++){
        float e = Esm[nn*EDIM + d];
        a.x += e*w[d].x; a.y += e*w[d].y; a.z += e*w[d].z; a.w += e*w[d].w;
      }
      __half2 h01 = __floats2half2_rn(a.x, a.y);
      __half2 h23 = __floats2half2_rn(a.z, a.w);
      *(uint2*)&Wn[((size_t)(n0+nn)*256 + i2)*OC + oq*4] =
          make_uint2(*(uint32_t*)&h01, *(uint32_t*)&h23);
    }
  }
}

// Merged (R12 champion): every 3rd block wgen (512), rest supmask (1024 x 16 rows).
__global__ void __launch_bounds__(256) k_sup_wgen(
    const float* __restrict__ T, const float* __restrict__ TP,
    const float* __restrict__ gamma, const float* __restrict__ beta,
    float* __restrict__ out_mask,
    const float* __restrict__ Wpr, const float* __restrict__ Wpu){
  __shared__ float Esm[64*EDIM];
  __shared__ float red[8][8];
  __shared__ float inv8[8];
  int bid = blockIdx.x;
  if (bid % 3 == 0){
    int lb = bid/3;
    if (lb < 256) wgen_body<128>(Wpr, g_Wn_r, lb, Esm);
    else          wgen_body<64>(Wpu, g_Wn_u, lb-256, Esm);
    return;
  }
  int id = bid - bid/3 - 1;                 // [0,1024)
  int b = id >> 6;
  int n0base = (id & 63)*16;
  extern __shared__ float sm[];
  float* Tsm = sm;                          // 48 KB
  int tid = threadIdx.x, lane = tid & 31, wrp = tid >> 5;
  {
    const float4* Tg = (const float4*)(T + (size_t)b*WINDOW*NN_);
    float4* T4 = (float4*)Tsm;
    #pragma unroll
    for (int i=0;i<12;i++) T4[tid + i*256] = Tg[tid + i*256];
  }
  __syncthreads();
  int m0 = tid*4;
  const float bni = 1.0f/sqrtf(1.0f + 1e-5f);
  unsigned int cnt = 0;
  #pragma unroll 1
  for (int half=0; half<2; half++){
    int n0 = n0base + half*8;
    float tg[8][4];
    #pragma unroll
    for (int r=0;r<8;r++){ tg[r][0]=0.f; tg[r][1]=0.f; tg[r][2]=0.f; tg[r][3]=0.f; }
    #pragma unroll
    for (int w=0; w<WINDOW; w++){
      float4 tw = *(float4*)&Tsm[w*NN_+m0];
      #pragma unroll
      for (int r=0;r<8;r++){
        float tvs = Tsm[w*NN_ + n0 + r];
        tg[r][0] += tvs*tw.x; tg[r][1] += tvs*tw.y;
        tg[r][2] += tvs*tw.z; tg[r][3] += tvs*tw.w;
      }
    }
    float psum[8];
    #pragma unroll
    for (int r=0;r<8;r++){
      tg[r][0] = __expf(fmaxf(tg[r][0],0.f));
      tg[r][1] = __expf(fmaxf(tg[r][1],0.f));
      tg[r][2] = __expf(fmaxf(tg[r][2],0.f));
      tg[r][3] = __expf(fmaxf(tg[r][3],0.f));
      psum[r] = (tg[r][0]+tg[r][1])+(tg[r][2]+tg[r][3]);
    }
    #pragma unroll
    for (int r=0;r<8;r++) psum[r] = warpSum(psum[r]);
    __syncthreads();
    if (lane==0){
      #pragma unroll
      for (int r=0;r<8;r++) red[r][wrp] = psum[r];
    }
    __syncthreads();
    if (tid < 8){
      float s = 0.f;
      #pragma unroll
      for (int k=0;k<8;k++) s += red[tid][k];
      inv8[tid] = 1.0f/s;
    }
    __syncthreads();
    float rm[8][4];
    #pragma unroll
    for (int r=0;r<8;r++){
      float4 t = *(const float4*)&g_EM[(size_t)(n0+r)*NN_ + m0];
      rm[r][0]=t.x; rm[r][1]=t.y; rm[r][2]=t.z; rm[r][3]=t.w;
    }
    #pragma unroll
    for (int w=0; w<WINDOW; w++){
      float4 tp = __ldg((const float4*)&TP[w*NN_+m0]);
      #pragma unroll
      for (int r=0;r<8;r++){
        float tvs = Tsm[w*NN_ + n0 + r];
        rm[r][0] += tvs*tp.x; rm[r][1] += tvs*tp.y;
        rm[r][2] += tvs*tp.z; rm[r][3] += tvs*tp.w;
      }
    }
    #pragma unroll
    for (int r=0;r<8;r++){
      int n = n0 + r;
      float sc = bni*gamma[n], bt = beta[n];
      float v0 = rm[r][0]*sc + bt, v1 = rm[r][1]*sc + bt;
      float v2 = rm[r][2]*sc + bt, v3 = rm[r][3]*sc + bt;
      uint32_t nib = (v0 > MASK_THR ? 1u:0u) | (v1 > MASK_THR ? 2u:0u)
                   | (v2 > MASK_THR ? 4u:0u) | (v3 > MASK_THR ? 8u:0u);
      float4 mk = make_float4(nib&1u?1.f:0.f, nib&2u?1.f:0.f, nib&4u?1.f:0.f, nib&8u?1.f:0.f);
      size_t idx = (size_t)b*NNSQ + (size_t)n*NN_ + m0;
      *(float4*)&out_mask[idx] = mk;
      float inv = inv8[r];
      float4 sp = *(const float4*)&g_supports[n*NN_+m0];
      sp.x = (sp.x + tg[r][0]*inv)*0.5f*mk.x;
      sp.y = (sp.y + tg[r][1]*inv)*0.5f*mk.y;
      sp.z = (sp.z + tg[r][2]*inv)*0.5f*mk.z;
      sp.w = (sp.w + tg[r][3]*inv)*0.5f*mk.w;
      *(uint2*)&g_sh[idx] = make_uint2(
          pack_h2(__float2half_rn(sp.x), __float2half_rn(sp.y)),
          pack_h2(__float2half_rn(sp.z), __float2half_rn(sp.w)));
      cnt += __popc(nib);
      uint32_t v = nib << ((lane&7)*4);
      v |= __shfl_xor_sync(0xffffffffu, v, 1);
      v |= __shfl_xor_sync(0xffffffffu, v, 2);
      v |= __shfl_xor_sync(0xffffffffu, v, 4);
      if ((lane&7)==0) g_bits[idx>>5] = v;
    }
  }
  __syncthreads();
  float fc = blockSum((float)cnt, (float*)red);
  if (tid==0) atomicAdd(&g_pos[b], (unsigned int)(fc + 0.5f));
}

// kept-count: forked on s2.
__global__ void __launch_bounds__(256) k_kept(){
  __shared__ unsigned int cnt[BB];
  if (threadIdx.x < BB) cnt[threadIdx.x] = 0u;
  __syncthreads();
  float prob = prob_from_pos();
  int lane = threadIdx.x & 31;
  unsigned int base = blockIdx.x*1024u + threadIdx.x;
  #pragma unroll
  for (int k=0;k<4;k++){
    unsigned int t = base + (unsigned)k*256u;
    uint32_t x0 = t, x1 = t + (uint32_t)HALF_BNN;
    threefry2x32(0u, 42u, x0, x1);
    float u0 = __uint_as_float((x0>>9) | 0x3f800000u) - 1.0f;
    float u1 = __uint_as_float((x1>>9) | 0x3f800000u) - 1.0f;
    uint32_t w0 = g_bits[t>>5];
    uint32_t w1 = g_bits[(t + HALF_BNN)>>5];
    int b0 = (int)(t >> 20);
    bool keep0 = ((w0>>lane)&1u) && !(u0 < prob);
    bool keep1 = ((w1>>lane)&1u) && !(u1 < prob);
    unsigned bal0 = __ballot_sync(0xffffffffu, keep0);
    unsigned bal1 = __ballot_sync(0xffffffffu, keep1);
    if (lane==0){
      if (bal0) atomicAdd(&cnt[b0],   __popc(bal0));
      if (bal1) atomicAdd(&cnt[b0+8], __popc(bal1));
    }
  }
  __syncthreads();
  if (threadIdx.x < BB && cnt[threadIdx.x]) atomicAdd(&g_kept[threadIdx.x], cnt[threadIdx.x]);
}

// mma<128> (R12 champion): 128 blocks, 512 threads, 128-row tiles, double-buffered.
__global__ void __launch_bounds__(512) k_mma128(const __half* __restrict__ Bh,
                                                const __half* __restrict__ Bl,
                                                float* __restrict__ C){
  constexpr int NO = 128;
  constexpr int BST = NO+8;
  constexpr int APITCH = 40;
  __shared__ __half Ash[2][128*APITCH];
  __shared__ __half Bsh[2][32*BST], Bsl[2][32*BST];
  int b = blockIdx.x >> 3;
  int m0 = (blockIdx.x & 7)*128;
  int w = threadIdx.x>>5, lane = threadIdx.x&31;
  int wm = (w>>1)*16;
  int wn = (w&1)*64;
  float acc[8][4];
  #pragma unroll
  for (int j=0;j<8;j++){ acc[j][0]=0.f; acc[j][1]=0.f; acc[j][2]=0.f; acc[j][3]=0.f; }
  const __half* Ahb = g_sh + (size_t)b*NNSQ;
  const __half* Bhb = Bh + (size_t)b*NN_*NO;
  const __half* Blb = Bl + (size_t)b*NN_*NO;
  int ar = threadIdx.x>>2, ac = threadIdx.x&3;
  int brr = threadIdx.x>>4, bc = threadIdx.x&15;
  uint4 pAh, pBh, pBl;
  auto ldtile = [&](int k0){
    pAh = *(const uint4*)&Ahb[(size_t)(m0+ar)*NN_ + k0 + ac*8];
    pBh = *(const uint4*)&Bhb[(size_t)(k0+brr)*NO + bc*8];
    pBl = *(const uint4*)&Blb[(size_t)(k0+brr)*NO + bc*8];
  };
  auto sttile = [&](int buf){
    *(uint4*)&Ash[buf][ar*APITCH + ac*8] = pAh;
    *(uint4*)&Bsh[buf][brr*BST + bc*8] = pBh;
    *(uint4*)&Bsl[buf][brr*BST + bc*8] = pBl;
  };
  ldtile(0);
  sttile(0);
  __syncthreads();
  #pragma unroll 1
  for (int t=0;t<32;t++){
    if (t+1 < 32) ldtile((t+1)*32);
    int buf = t & 1;
    #pragma unroll
    for (int kk=0; kk<2; kk++){
      uint32_t ah[4];
      int aoff = (wm + (lane&15))*APITCH + kk*16 + (lane>>4)*8;
      ldsm4(ah[0],ah[1],ah[2],ah[3], &Ash[buf][aoff]);
      #pragma unroll
      for (int j=0;j<8;j++){
        uint32_t bh[2], bl[2];
        int boff = (kk*16 + (lane&15))*BST + wn + j*8;
        ldsm2t(bh[0],bh[1], &Bsh[buf][boff]);
        ldsm2t(bl[0],bl[1], &Bsl[buf][boff]);
        mma16816h(acc[j], ah, bh);
        mma16816h(acc[j], ah, bl);
      }
    }
    if (t+1 < 32){
      __syncthreads();
      sttile((t+1)&1);
      __syncthreads();
    }
  }
  #pragma unroll
  for (int j=0;j<8;j++){
    int r0 = m0 + wm + (lane>>2);
    int c0 = wn + j*8 + (lane&3)*2;
    float* Cp = C + ((size_t)b*NN_ + r0)*NO + c0;
    Cp[0] = acc[j][0]; Cp[1] = acc[j][1];
    Cp[(size_t)8*NO] = acc[j][2]; Cp[(size_t)8*NO+1] = acc[j][3];
  }
}

// mma<64>: 256 threads, A=fp16 single, B=fp16 hi/lo.
__global__ void k_mma64(const __half* __restrict__ Bh,
                        const __half* __restrict__ Bl,
                        float* __restrict__ C){
  constexpr int NO = 64;
  constexpr int BST = NO+8;
  __shared__ __half Ash[128*40];
  __shared__ __half Bsh[32*BST], Bsl[32*BST];
  int b = blockIdx.y;
  int m0 = blockIdx.x*128;
  int w = threadIdx.x>>5, lane = threadIdx.x&31;
  int wm = w*16;
  float acc[8][4];
  #pragma unroll
  for (int j=0;j<8;j++){ acc[j][0]=0.f; acc[j][1]=0.f; acc[j][2]=0.f; acc[j][3]=0.f; }
  const __half* Ahb = g_sh + (size_t)b*NNSQ;
  const __half* Bhb = Bh + (size_t)b*NN_*NO;
  const __half* Blb = Bl + (size_t)b*NN_*NO;
  for (int k0=0;k0<NN_;k0+=32){
    #pragma unroll
    for (int i = threadIdx.x; i<512; i+=256){
      int r = i>>2, c = i&3;
      *(uint4*)&Ash[r*40 + c*8] = *(const uint4*)&Ahb[(size_t)(m0+r)*NN_ + k0 + c*8];
    }
    {
      int i = threadIdx.x;
      int r = i>>3, c = i&7;
      *(uint4*)&Bsh[r*BST + c*8] = *(const uint4*)&Bhb[(size_t)(k0+r)*NO + c*8];
      *(uint4*)&Bsl[r*BST + c*8] = *(const uint4*)&Blb[(size_t)(k0+r)*NO + c*8];
    }
    __syncthreads();
    #pragma unroll
    for (int kk=0; kk<2; kk++){
      uint32_t ah[4];
      int aoff = (wm + (lane&15))*40 + kk*16 + (lane>>4)*8;
      ldsm4(ah[0],ah[1],ah[2],ah[3], &Ash[aoff]);
      #pragma unroll
      for (int j=0;j<8;j++){
        uint32_t bh[2], bl[2];
        int boff = (kk*16 + (lane&15))*BST + j*8;
        ldsm2t(bh[0],bh[1], &Bsh[boff]);
        ldsm2t(bl[0],bl[1], &Bsl[boff]);
        mma16816h(acc[j], ah, bh);
        mma16816h(acc[j], ah, bl);
      }
    }
    __syncthreads();
  }
  #pragma unroll
  for (int j=0;j<8;j++){
    int r0 = m0 + wm + (lane>>2);
    int c0 = j*8 + (lane&3)*2;
    float* Cp = C + ((size_t)b*NN_ + r0)*NO + c0;
    Cp[0] = acc[j][0]; Cp[1] = acc[j][1];
    Cp[(size_t)8*NO] = acc[j][2]; Cp[(size_t)8*NO+1] = acc[j][3];
  }
}

// r-gate: 4b x 4o register tile; W fp16; 4-way batched loads.
__global__ void __launch_bounds__(128) k_gate_r(const float* __restrict__ x,
                                                const float* __restrict__ st){
  int n = blockIdx.x;
  __shared__ float Xg[256*20];
  int t = threadIdx.x;
  for (int q=t; q<4096; q+=128){
    int b = q>>8, i = q&255;
    float v;
    if (i < 64)       v = x[((size_t)b*NN_+n)*64 + i];
    else if (i < 128) v = st[((size_t)b*NN_+n)*64 + (i-64)];
    else              v = g_xb[((size_t)b*NN_+n)*128 + (i-128)];
    Xg[i*20 + b] = v;
  }
  __syncthreads();
  int og = t>>2, bg = t&3;
  int o0 = og*4, b0 = bg*4;
  float acc[4][4] = {};
  const __half* W = g_Wn_r + (size_t)n*256*128 + o0;
  #pragma unroll 1
  for (int i=0;i<256;i+=4){
    uint2 wv[4]; float4 xv[4];
    #pragma unroll
    for (int u=0;u<4;u++){
      wv[u] = *(const uint2*)&W[(size_t)(i+u)*128];
      xv[u] = *(float4*)&Xg[(i+u)*20 + b0];
    }
    #pragma unroll
    for (int u=0;u<4;u++){
      float2 f01 = __half22float2(*(__half2*)&wv[u].x);
      float2 f23 = __half22float2(*(__half2*)&wv[u].y);
      float xs[4] = {xv[u].x,xv[u].y,xv[u].z,xv[u].w};
      float ws[4] = {f01.x,f01.y,f23.x,f23.y};
      #pragma unroll
      for (int bi=0;bi<4;bi++)
        #pragma unroll
        for (int oi=0;oi<4;oi++)
          acc[bi][oi] += xs[bi]*ws[oi];
    }
  }
  float4 bias = *(const float4*)&g_bias_r[n*128 + o0];
  float bs[4] = {bias.x,bias.y,bias.z,bias.w};
  #pragma unroll
  for (int bi=0;bi<4;bi++){
    int b = b0+bi;
    size_t idx = ((size_t)b*NN_+n)*64;
    #pragma unroll
    for (int oi=0;oi<4;oi++){
      int o = o0+oi;
      float g = 1.0f/(1.0f+__expf(-(acc[bi][oi]+bs[oi])));
      if (o < 64){
        float zsv = g * st[idx + o];
        g_zs[idx + o] = zsv;
        __half h, l; split_h16(zsv, h, l);
        g_zh[idx + o] = h; g_zl[idx + o] = l;
      } else {
        g_rb[idx + (o-64)] = g;
      }
    }
  }
}

// u-gate + GRU output; block 1024 computes mask_loss. W fp16; 4-way batched loads.
__global__ void __launch_bounds__(128) k_gate_u(const float* __restrict__ x,
                                                const float* __restrict__ st,
                                                float* __restrict__ out_h,
                                                float* __restrict__ out_loss){
  if (blockIdx.x == NN_){
    if (threadIdx.x < BB){
      unsigned int tot = 0;
      #pragma unroll
      for (int i=0;i<BB;i++) tot += g_pos[i];
      float active = (float)tot / (float)BNN;
      float addend = fmaxf(0.05f/active - 1.0f, 0.0f);
      int b = threadIdx.x;
      out_loss[b] = (float)g_kept[b] / ((float)g_pos[b] + 1e-8f) + addend;
    }
    return;
  }
  int n = blockIdx.x;
  __shared__ float Xg[256*20];
  int t = threadIdx.x;
  for (int q=t; q<4096; q+=128){
    int b = q>>8, i = q&255;
    float v;
    if (i < 64)       v = x[((size_t)b*NN_+n)*64 + i];
    else if (i < 128) v = g_zs[((size_t)b*NN_+n)*64 + (i-64)];
    else if (i < 192) v = g_xb[((size_t)b*NN_+n)*128 + (i-128)];
    else              v = g_c2[((size_t)b*NN_+n)*64 + (i-192)];
    Xg[i*20 + b] = v;
  }
  __syncthreads();
  int og = t>>3, bg = t&7;
  int o0 = og*4, b0 = bg*2;
  float acc[2][4] = {};
  const __half* W = g_Wn_u + (size_t)n*256*64 + o0;
  #pragma unroll 1
  for (int i=0;i<256;i+=4){
    uint2 wv[4]; float2 xv[4];
    #pragma unroll
    for (int u=0;u<4;u++){
      wv[u] = *(const uint2*)&W[(size_t)(i+u)*64];
      xv[u] = *(float2*)&Xg[(i+u)*20 + b0];
    }
    #pragma unroll
    for (int u=0;u<4;u++){
      float2 f01 = __half22float2(*(__half2*)&wv[u].x);
      float2 f23 = __half22float2(*(__half2*)&wv[u].y);
      float xs[2] = {xv[u].x,xv[u].y};
      float ws[4] = {f01.x,f01.y,f23.x,f23.y};
      #pragma unroll
      for (int bi=0;bi<2;bi++)
        #pragma unroll
        for (int oi=0;oi<4;oi++)
          acc[bi][oi] += xs[bi]*ws[oi];
    }
  }
  float4 bias = *(const float4*)&g_bias_u[n*64 + o0];
  float bs[4] = {bias.x,bias.y,bias.z,bias.w};
  #pragma unroll
  for (int bi=0;bi<2;bi++){
    int b = b0+bi;
    size_t idx = ((size_t)b*NN_+n)*64;
    #pragma unroll
    for (int oi=0;oi<4;oi++){
      int o = o0+oi;
      float hc = tanhf(acc[bi][oi]+bs[oi]);
      float r = g_rb[idx + o];
      float sv = st[idx + o];
      out_h[idx + o] = r*sv + (1.0f-r)*hc;
    }
  }
}

// ---------------- launch ----------------
extern "C" void kernel_launch(void* const* d_in, const int* in_sizes, int n_in,
                              void* d_out, int out_size){
  const float* x    = (const float*)d_in[0];
  const float* st   = (const float*)d_in[1];
  const float* we   = (const float*)d_in[2];
  const float* T    = (const float*)d_in[3];
  const float* Wpr  = (const float*)d_in[4];
  const float* bpr  = (const float*)d_in[5];
  const float* Wpu  = (const float*)d_in[6];
  const float* bpu  = (const float*)d_in[7];
  const float* mp   = (const float*)d_in[8];
  const float* tp   = (const float*)d_in[9];
  const float* gmm  = (const float*)d_in[10];
  const float* bta  = (const float*)d_in[11];
  const int*   itp  = (const int*)d_in[12];
  float* out = (float*)d_out;
  float* out_mask = out + OFF_MASK;

  static __half *xh_p=nullptr, *xl_p=nullptr, *zh_p=nullptr, *zl_p=nullptr;
  static float *xb_p=nullptr, *c2_p=nullptr;
  static cudaStream_t s2 = nullptr;
  static cudaEvent_t evF = nullptr, evP = nullptr, evFork = nullptr, evJoin = nullptr;
  if (!xh_p){
    cudaGetSymbolAddress((void**)&xh_p, g_xh);
    cudaGetSymbolAddress((void**)&xl_p, g_xl);
    cudaGetSymbolAddress((void**)&zh_p, g_zh);
    cudaGetSymbolAddress((void**)&zl_p, g_zl);
    cudaGetSymbolAddress((void**)&xb_p, g_xb);
    cudaGetSymbolAddress((void**)&c2_p, g_c2);
    size_t smem_sup = (size_t)(WINDOW*NN_)*sizeof(float);   // 48 KB
    cudaFuncSetAttribute(k_sup_wgen, cudaFuncAttributeMaxDynamicSharedMemorySize, (int)smem_sup);
    cudaStreamCreateWithFlags(&s2, cudaStreamNonBlocking);
    cudaEventCreateWithFlags(&evF, cudaEventDisableTiming);
    cudaEventCreateWithFlags(&evP, cudaEventDisableTiming);
    cudaEventCreateWithFlags(&evFork, cudaEventDisableTiming);
    cudaEventCreateWithFlags(&evJoin, cudaEventDisableTiming);
  }
  size_t smem_sup = (size_t)(WINDOW*NN_)*sizeof(float);

  k_setup<<<64,256>>>(we, itp);                            // main
  cudaEventRecord(evF, 0);
  cudaStreamWaitEvent(s2, evF, 0);
  k_prep<<<2048,256,0,s2>>>(x, st);                        // s2
  cudaEventRecord(evP, s2);
  k_pre<<<2048,256>>>(mp, bpr, bpu);                       // main
  k_sup_wgen<<<1536,256,smem_sup>>>(T, tp, gmm, bta, out_mask, Wpr, Wpu); // main (profiled)
  cudaEventRecord(evFork, 0);
  cudaStreamWaitEvent(s2, evFork, 0);
  k_kept<<<8192,256,0,s2>>>();                             // s2
  cudaEventRecord(evJoin, s2);
  cudaStreamWaitEvent(0, evP, 0);
  k_mma128<<<128,512>>>(xh_p, xl_p, xb_p);                 // main (R12 config)
  k_gate_r<<<NN_,128>>>(x, st);                            // main
  k_mma64<<<dim3(8,16),256>>>(zh_p, zl_p, c2_p);           // main
  cudaStreamWaitEvent(0, evJoin, 0);
  k_gate_u<<<NN_+1,128>>>(x, st, out, out + OFF_LOSS);     // main
}